// round 14
// baseline (speedup 1.0000x reference)
#include <cuda_runtime.h>
#include <math.h>
#include <stdint.h>

#define IMGS   457
#define HPAD   464
#define HP     29
#define NTOK   841
#define BATCH  8
#define DIM    256
#define MTOK   (BATCH*NTOK)   // 6728
#define NHEADS 8
#define DH     32

// ---------------- scratch (device globals; no allocations) ----------------
__device__ float g_t   [MTOK*DIM];
__device__ float g_qkv [MTOK*768];
__device__ float g_attn[MTOK*DIM];
__device__ float g_ff  [MTOK*1024];

// pre-truncated (tf32) weights, with LN gamma folded into qkv/ff1
#define W_SPT_OFF  0
#define W_SPT_SZ   (256*1280)
#define W_QKV_OFF  (W_SPT_OFF+W_SPT_SZ)
#define W_QKV_SZ   (3*768*256)
#define W_WOUT_OFF (W_QKV_OFF+W_QKV_SZ)
#define W_WOUT_SZ  (3*256*256)
#define W_FF1_OFF  (W_WOUT_OFF+W_WOUT_SZ)
#define W_FF1_SZ   (3*1024*256)
#define W_FF2_OFF  (W_FF1_OFF+W_FF1_SZ)
#define W_FF2_SZ   (3*256*1024)
#define W_PIX_OFF  (W_FF2_OFF+W_FF2_SZ)
#define W_PIX_SZ   (256*256)
#define W_TOTAL    (W_PIX_OFF+W_PIX_SZ)
__device__ float g_wtf[W_TOTAL];

// per-layer LN column terms: [layer][ qkv 768 | ff1 1024 ]
#define LNC_PER 1792
__device__ float g_lnS[3*LNC_PER];
__device__ float g_lnB[3*LNC_PER];

__device__ __forceinline__ uint32_t f2tf(float f) {
    uint32_t r;
    asm("cvt.rna.tf32.f32 %0, %1;" : "=r"(r) : "f"(f));
    return r;
}
__device__ __forceinline__ float ftrunc_tf(float f) { return __uint_as_float(f2tf(f)); }

// ---------- weight conversion: tf32 truncate + fold LN gamma --------------
__global__ void convert_w(const float* __restrict__ spt, const float* __restrict__ qkv,
                          const float* __restrict__ wo, const float* __restrict__ f1,
                          const float* __restrict__ f2w, const float* __restrict__ px,
                          const float* __restrict__ ln1w, const float* __restrict__ ln2w) {
    int i4 = blockIdx.x * 256 + threadIdx.x;
    if (i4 >= W_TOTAL / 4) return;
    int i = i4 * 4;
    const float* src; int off;
    if      (i < W_QKV_OFF)  { src = spt; off = 0; }
    else if (i < W_WOUT_OFF) { src = qkv; off = W_QKV_OFF; }
    else if (i < W_FF1_OFF)  { src = wo;  off = W_WOUT_OFF; }
    else if (i < W_FF2_OFF)  { src = f1;  off = W_FF1_OFF; }
    else if (i < W_PIX_OFF)  { src = f2w; off = W_FF2_OFF; }
    else                     { src = px;  off = W_PIX_OFF; }
    float4 v = *(const float4*)(src + (i - off));
    // fold LN gamma into qkv (ln1_w) and ff1 (ln2_w): column-scale by gamma[k]
    if (i >= W_QKV_OFF && i < W_WOUT_OFF) {
        int rel = i - W_QKV_OFF;
        int d = rel / (768 * 256);
        int k = rel & 255;
        float4 g = *(const float4*)(ln1w + d * 256 + k);
        v.x *= g.x; v.y *= g.y; v.z *= g.z; v.w *= g.w;
    } else if (i >= W_FF1_OFF && i < W_FF2_OFF) {
        int rel = i - W_FF1_OFF;
        int d = rel / (1024 * 256);
        int k = rel & 255;
        float4 g = *(const float4*)(ln2w + d * 256 + k);
        v.x *= g.x; v.y *= g.y; v.z *= g.z; v.w *= g.w;
    }
    v.x = ftrunc_tf(v.x); v.y = ftrunc_tf(v.y);
    v.z = ftrunc_tf(v.z); v.w = ftrunc_tf(v.w);
    *(float4*)&g_wtf[i] = v;
}

// ---------- colsum: S[n] = sum_k W'[n,k];  B2[n] = sum_k W[n,k]*beta[k] ---
__global__ void colsum_kernel(const float* __restrict__ wqkv, const float* __restrict__ f1w,
                              const float* __restrict__ ln1b, const float* __restrict__ ln2b) {
    int n = blockIdx.x * 8 + (threadIdx.x >> 5);
    if (n >= 3 * LNC_PER) return;
    int d = n / LNC_PER, r = n % LNC_PER;
    const float* wt; const float* worig; const float* bln;
    if (r < 768) {
        wt = g_wtf + W_QKV_OFF + (size_t)d * 768 * 256 + (size_t)r * 256;
        worig = wqkv + (size_t)d * 768 * 256 + (size_t)r * 256;
        bln = ln1b + d * 256;
    } else {
        int rr = r - 768;
        wt = g_wtf + W_FF1_OFF + (size_t)d * 1024 * 256 + (size_t)rr * 256;
        worig = f1w + (size_t)d * 1024 * 256 + (size_t)rr * 256;
        bln = ln2b + d * 256;
    }
    int lane = threadIdx.x & 31;
    float s = 0.f, b = 0.f;
    #pragma unroll
    for (int k = lane; k < 256; k += 32) { s += wt[k]; b += worig[k] * bln[k]; }
    #pragma unroll
    for (int o = 16; o; o >>= 1) {
        s += __shfl_xor_sync(0xffffffffu, s, o);
        b += __shfl_xor_sync(0xffffffffu, b, o);
    }
    if (lane == 0) { g_lnS[n] = s; g_lnB[n] = b; }
}

// ---------------- tf32 tensor-core GEMM, BM=64, 3-stage cp.async, LDSM ----
__device__ __forceinline__ void mma_tf32(float c[4], const uint32_t a[4],
                                         uint32_t b0, uint32_t b1) {
    asm volatile(
        "mma.sync.aligned.m16n8k8.row.col.f32.tf32.tf32.f32 "
        "{%0,%1,%2,%3}, {%4,%5,%6,%7}, {%8,%9}, {%0,%1,%2,%3};"
        : "+f"(c[0]), "+f"(c[1]), "+f"(c[2]), "+f"(c[3])
        : "r"(a[0]), "r"(a[1]), "r"(a[2]), "r"(a[3]), "r"(b0), "r"(b1));
}
__device__ __forceinline__ float gelu_exact(float v) {
    return 0.5f * v * (1.0f + erff(v * 0.70710678118654752440f));
}
__device__ __forceinline__ void cp16(uint32_t saddr, const float* g, bool pred) {
    asm volatile("cp.async.cg.shared.global [%0], [%1], 16, %2;"
                 :: "r"(saddr), "l"(g), "r"(pred ? 16 : 0));
}
__device__ __forceinline__ void cp4(uint32_t saddr, const float* g, bool pred) {
    asm volatile("cp.async.ca.shared.global [%0], [%1], 4, %2;"
                 :: "r"(saddr), "l"(g), "r"(pred ? 4 : 0));
}
__device__ __forceinline__ void cp_commit() { asm volatile("cp.async.commit_group;"); }
template<int N>
__device__ __forceinline__ void cp_wait() {
    asm volatile("cp.async.wait_group %0;" :: "n"(N));
}
__device__ __forceinline__ int swz(int row, int col) {
    return row * 32 + (col ^ ((row & 7) * 4));
}
__device__ __forceinline__ void ldsm4(uint32_t addr, uint32_t& r0, uint32_t& r1,
                                      uint32_t& r2, uint32_t& r3) {
    asm volatile("ldmatrix.sync.aligned.m8n8.x4.shared.b16 {%0,%1,%2,%3}, [%4];"
                 : "=r"(r0), "=r"(r1), "=r"(r2), "=r"(r3) : "r"(addr));
}

#define GEMM_SMEM (3 * (64 * 32 + 4096) * 4)   // 73728 B

template<int MINB, int ACT, bool HASBIAS, bool HASRES, bool POSMOD, bool TRUNC,
         bool GATHER, bool RESHAPE, bool LNFUSE>
__global__ void __launch_bounds__(256, MINB)
gemm_tc(const float* __restrict__ A, const float* __restrict__ W,
        const float* __restrict__ bias, const float* __restrict__ res,
        float* __restrict__ C, const float* __restrict__ Sarr,
        const float* __restrict__ Barr, int M, int Nn, int K) {
    constexpr int BM = 64;
    constexpr int NWM = 2;
    constexpr int WN  = 32;
    constexpr int NP  = 2;
    constexpr int NT  = 4;
    constexpr int ASTG = BM * 32;

    extern __shared__ float smem[];
    float* As = smem;
    float* Ws = smem + 3 * ASTG;
    const int tid  = threadIdx.x;
    const int wid  = tid >> 5, lane = tid & 31;
    const int wm   = wid % NWM, wn = wid / NWM;
    const int gid  = lane >> 2, tig = lane & 3;
    const int m0   = blockIdx.y * BM, n0 = blockIdx.x * 128;

    const int lrow = tid >> 3;
    const int lc4  = (tid & 7) * 4;

    uint32_t As_base = (uint32_t)__cvta_generic_to_shared(As);
    uint32_t Ws_base = (uint32_t)__cvta_generic_to_shared(Ws);

    const int rowA_in  = (lane & 15);
    const int koffA    = ((lane >> 4) & 1) * 4;
    const int rowB_in  = (lane & 7) + (((lane >> 4) & 1) << 3);
    const int koffB    = ((lane >> 3) & 1) * 4;

    bool grow[2];
    int  gb[2], gpy[2], gpx[2];
    if (GATHER) {
        #pragma unroll
        for (int i = 0; i < 2; i++) {
            int m = m0 + lrow + i * 32;
            grow[i] = m < M;
            int mm = m < M ? m : (M - 1);
            gb[i] = mm / NTOK;
            int n8 = mm - gb[i] * NTOK;
            gpy[i] = n8 / HP;
            gpx[i] = n8 - gpy[i] * HP;
        }
    }

    float acc[2][NT][4] = {};
    float st[2][2] = {}, sq[2][2] = {};   // LNFUSE row stats
    const int ktiles = K >> 5;

    auto load_tile = [&](int kt, int buf) {
        if (GATHER) {
            int c  = kt * 32 + lc4;
            int s  = c >> 8;
            int pr = (c >> 4) & 15;
            int pc = c & 15;
            int dy = (s == 0) ? 0 : ((s <= 2) ? -8 : 8);
            int dx = (s == 0) ? 0 : ((s & 1) ? -8 : 8);
            #pragma unroll
            for (int i = 0; i < 2; i++) {
                int row = lrow + i * 32;
                uint32_t sdst = As_base + (buf * ASTG + swz(row, lc4)) * 4;
                int y  = gpy[i] * 16 + pr - dy;
                if (y < 0) y += HPAD; if (y >= HPAD) y -= HPAD;
                int xx = gpx[i] * 16 + pc - dx;
                if (xx < 0) xx += HPAD; if (xx >= HPAD) xx -= HPAD;
                bool yv = grow[i] && (y < IMGS);
                const float* src = A + ((size_t)gb[i] * IMGS + y) * IMGS + xx;
                #pragma unroll
                for (int q = 0; q < 4; q++)
                    cp4(sdst + q * 4, src + q, yv && (xx + q) < IMGS);
            }
        } else {
            const float* Ag = A + (size_t)m0 * K + kt * 32;
            #pragma unroll
            for (int i = 0; i < 2; i++) {
                int row = lrow + i * 32;
                uint32_t s = As_base + (buf * ASTG + swz(row, lc4)) * 4;
                cp16(s, Ag + (size_t)row * K + lc4, (m0 + row) < M);
            }
        }
        const float* Wg = W + (size_t)n0 * K + kt * 32;
        #pragma unroll
        for (int i = 0; i < 4; i++) {
            int row = lrow + i * 32;
            uint32_t s = Ws_base + (buf * 4096 + swz(row, lc4)) * 4;
            cp16(s, Wg + (size_t)row * K + lc4, true);
        }
    };

    load_tile(0, 0);
    cp_commit();
    if (ktiles > 1) { load_tile(1, 1); cp_commit(); }

    for (int kt = 0; kt < ktiles; kt++) {
        if (kt + 2 < ktiles) {
            load_tile(kt + 2, (kt + 2) % 3);
            cp_commit();
            cp_wait<2>();
        } else if (kt + 1 < ktiles) {
            cp_wait<1>();
        } else {
            cp_wait<0>();
        }
        __syncthreads();

        const uint32_t as_b = As_base + ((kt % 3) * ASTG) * 4;
        const uint32_t ws_b = Ws_base + ((kt % 3) * 4096) * 4;
        #pragma unroll
        for (int ks = 0; ks < 32; ks += 8) {
            uint32_t af[2][4];
            #pragma unroll
            for (int mt = 0; mt < 2; mt++) {
                int row = wm * 32 + mt * 16 + rowA_in;
                int col = ks + koffA;
                uint32_t addr = as_b + (uint32_t)swz(row, col) * 4;
                ldsm4(addr, af[mt][0], af[mt][1], af[mt][2], af[mt][3]);
                if (LNFUSE) {
                    float v0 = __uint_as_float(af[mt][0]);
                    float v1 = __uint_as_float(af[mt][1]);
                    float v2 = __uint_as_float(af[mt][2]);
                    float v3 = __uint_as_float(af[mt][3]);
                    st[mt][0] += v0 + v2;
                    st[mt][1] += v1 + v3;
                    sq[mt][0] = fmaf(v0, v0, fmaf(v2, v2, sq[mt][0]));
                    sq[mt][1] = fmaf(v1, v1, fmaf(v3, v3, sq[mt][1]));
                }
            }
            #pragma unroll
            for (int np = 0; np < NP; np++) {
                int row = wn * WN + np * 16 + rowB_in;
                int col = ks + koffB;
                uint32_t addr = ws_b + (uint32_t)swz(row, col) * 4;
                uint32_t b0a, b1a, b0b, b1b;
                ldsm4(addr, b0a, b1a, b0b, b1b);
                mma_tf32(acc[0][2 * np    ], af[0], b0a, b1a);
                mma_tf32(acc[1][2 * np    ], af[1], b0a, b1a);
                mma_tf32(acc[0][2 * np + 1], af[0], b0b, b1b);
                mma_tf32(acc[1][2 * np + 1], af[1], b0b, b1b);
            }
        }
        __syncthreads();
    }

    float aa[2][2], cc[2][2];
    if (LNFUSE) {
        const float inv = 1.f / (float)K;
        #pragma unroll
        for (int mt = 0; mt < 2; mt++) {
            #pragma unroll
            for (int hf = 0; hf < 2; hf++) {
                float s = st[mt][hf], q = sq[mt][hf];
                s += __shfl_xor_sync(0xffffffffu, s, 1);
                s += __shfl_xor_sync(0xffffffffu, s, 2);
                q += __shfl_xor_sync(0xffffffffu, q, 1);
                q += __shfl_xor_sync(0xffffffffu, q, 2);
                float mean = s * inv;
                float var  = q * inv - mean * mean;
                float rstd = rsqrtf(var + 1e-5f);
                aa[mt][hf] = rstd;
                cc[mt][hf] = -mean * rstd;
            }
        }
    }

    #pragma unroll
    for (int mt = 0; mt < 2; mt++) {
        #pragma unroll
        for (int half = 0; half < 2; half++) {
            int m = m0 + wm * 32 + mt * 16 + gid + half * 8;
            if (m >= M) continue;
            int mres = POSMOD ? (m % NTOK) : m;
            int ob = 0, opy = 0, opx = 0;
            if (RESHAPE) {
                ob = m / NTOK;
                int n8 = m - ob * NTOK;
                opy = n8 / HP;
                opx = n8 - opy * HP;
            }
            #pragma unroll
            for (int nt = 0; nt < NT; nt++) {
                int n = n0 + wn * WN + nt * 8 + tig * 2;
                float v0 = acc[mt][nt][half * 2 + 0];
                float v1 = acc[mt][nt][half * 2 + 1];
                if (LNFUSE) {
                    float a = aa[mt][half], c = cc[mt][half];
                    float2 S = *(const float2*)&Sarr[n];
                    float2 B = *(const float2*)&Barr[n];
                    v0 = a * v0 + c * S.x + B.x;
                    v1 = a * v1 + c * S.y + B.y;
                }
                if (HASBIAS) { v0 += bias[n]; v1 += bias[n + 1]; }
                if (ACT == 1) { v0 = gelu_exact(v0); v1 = gelu_exact(v1); }
                if (HASRES) {
                    float2 r = *(const float2*)&res[(size_t)mres * Nn + n];
                    v0 += r.x; v1 += r.y;
                }
                if (TRUNC) { v0 = ftrunc_tf(v0); v1 = ftrunc_tf(v1); }
                if (RESHAPE) {
                    int y  = opy * 16 + (n >> 4);
                    int xc = opx * 16 + (n & 15);
                    if (y < IMGS) {
                        float* orow = C + ((size_t)ob * IMGS + y) * IMGS;
                        if (xc < IMGS)     orow[xc]     = v0;
                        if (xc + 1 < IMGS) orow[xc + 1] = v1;
                    }
                } else {
                    *(float2*)&C[(size_t)m * Nn + n] = make_float2(v0, v1);
                }
            }
        }
    }
}

// ---------------- MMA flash attention, q-tile 128, 8 warps ----------------
__global__ void __launch_bounds__(256)
attn_mma(const float* __restrict__ scale_d) {
    __shared__ uint32_t Ks[32 * 36];
    __shared__ uint32_t Vs[32 * 40];
    __shared__ uint32_t Ps[8][16 * 36];

    const int bh = blockIdx.y;
    const int b = bh >> 3, h = bh & 7;
    const int tid = threadIdx.x;
    const int warp = tid >> 5, lane = tid & 31;
    const int gid = lane >> 2, tig = lane & 3;
    const int q0 = (gridDim.x - 1 - blockIdx.x) * 128;
    const float* base = g_qkv + (size_t)b * NTOK * 768;
    const float sc = scale_d[h];

    const int i0 = q0 + warp * 16 + gid;
    const int i1 = i0 + 8;

    uint32_t qf[4][4];
    #pragma unroll
    for (int ks = 0; ks < 4; ks++) {
        int c = h * 32 + ks * 8 + tig;
        float v00 = 0.f, v10 = 0.f, v01 = 0.f, v11 = 0.f;
        if (i0 < NTOK) { v00 = base[(size_t)i0 * 768 + c] * sc;
                         v01 = base[(size_t)i0 * 768 + c + 4] * sc; }
        if (i1 < NTOK) { v10 = base[(size_t)i1 * 768 + c] * sc;
                         v11 = base[(size_t)i1 * 768 + c + 4] * sc; }
        qf[ks][0] = f2tf(v00); qf[ks][1] = f2tf(v10);
        qf[ks][2] = f2tf(v01); qf[ks][3] = f2tf(v11);
    }

    float m0 = -1e30f, m1 = -1e30f, l0 = 0.f, l1 = 0.f;
    float oacc[4][4] = {};

    const int jmax = min(q0 + 127, NTOK - 1);
    for (int j0 = 0; j0 < jmax; j0 += 32) {
        __syncthreads();
        {
            int r  = tid >> 3;
            int c4 = (tid & 7) * 4;
            int j  = j0 + r;
            if (j < NTOK) {
                const float* kp = base + (size_t)j * 768 + 256 + h * 32 + c4;
                const float* vp = base + (size_t)j * 768 + 512 + h * 32 + c4;
                float4 ka = *(const float4*)kp;
                Ks[r * 36 + c4 + 0] = f2tf(ka.x); Ks[r * 36 + c4 + 1] = f2tf(ka.y);
                Ks[r * 36 + c4 + 2] = f2tf(ka.z); Ks[r * 36 + c4 + 3] = f2tf(ka.w);
                float4 va = *(const float4*)vp;
                Vs[r * 40 + c4 + 0] = f2tf(va.x); Vs[r * 40 + c4 + 1] = f2tf(va.y);
                Vs[r * 40 + c4 + 2] = f2tf(va.z); Vs[r * 40 + c4 + 3] = f2tf(va.w);
            } else {
                #pragma unroll
                for (int q = 0; q < 4; q++) {
                    Ks[r * 36 + c4 + q] = 0;
                    Vs[r * 40 + c4 + q] = 0;
                }
            }
        }
        __syncthreads();

        float s[4][4] = {};
        #pragma unroll
        for (int ks = 0; ks < 4; ks++) {
            #pragma unroll
            for (int nt = 0; nt < 4; nt++) {
                uint32_t b0 = Ks[(nt * 8 + gid) * 36 + ks * 8 + tig];
                uint32_t b1 = Ks[(nt * 8 + gid) * 36 + ks * 8 + tig + 4];
                mma_tf32(s[nt], qf[ks], b0, b1);
            }
        }

        float rm0 = -1e30f, rm1 = -1e30f;
        #pragma unroll
        for (int nt = 0; nt < 4; nt++) {
            int jc = j0 + nt * 8 + tig * 2;
            if (jc     >= i0) s[nt][0] = -1e30f;
            if (jc + 1 >= i0) s[nt][1] = -1e30f;
            if (jc     >= i1) s[nt][2] = -1e30f;
            if (jc + 1 >= i1) s[nt][3] = -1e30f;
            rm0 = fmaxf(rm0, fmaxf(s[nt][0], s[nt][1]));
            rm1 = fmaxf(rm1, fmaxf(s[nt][2], s[nt][3]));
        }
        rm0 = fmaxf(rm0, __shfl_xor_sync(0xffffffffu, rm0, 1));
        rm0 = fmaxf(rm0, __shfl_xor_sync(0xffffffffu, rm0, 2));
        rm1 = fmaxf(rm1, __shfl_xor_sync(0xffffffffu, rm1, 1));
        rm1 = fmaxf(rm1, __shfl_xor_sync(0xffffffffu, rm1, 2));
        float mn0 = fmaxf(m0, rm0), mn1 = fmaxf(m1, rm1);
        float corr0 = __expf(m0 - mn0), corr1 = __expf(m1 - mn1);

        float p[4][4];
        float ps0 = 0.f, ps1 = 0.f;
        #pragma unroll
        for (int nt = 0; nt < 4; nt++) {
            p[nt][0] = (s[nt][0] < -1e29f) ? 0.f : __expf(s[nt][0] - mn0);
            p[nt][1] = (s[nt][1] < -1e29f) ? 0.f : __expf(s[nt][1] - mn0);
            p[nt][2] = (s[nt][2] < -1e29f) ? 0.f : __expf(s[nt][2] - mn1);
            p[nt][3] = (s[nt][3] < -1e29f) ? 0.f : __expf(s[nt][3] - mn1);
            ps0 += p[nt][0] + p[nt][1];
            ps1 += p[nt][2] + p[nt][3];
        }
        ps0 += __shfl_xor_sync(0xffffffffu, ps0, 1);
        ps0 += __shfl_xor_sync(0xffffffffu, ps0, 2);
        ps1 += __shfl_xor_sync(0xffffffffu, ps1, 1);
        ps1 += __shfl_xor_sync(0xffffffffu, ps1, 2);
        l0 = l0 * corr0 + ps0;
        l1 = l1 * corr1 + ps1;
        #pragma unroll
        for (int nt = 0; nt < 4; nt++) {
            oacc[nt][0] *= corr0; oacc[nt][1] *= corr0;
            oacc[nt][2] *= corr1; oacc[nt][3] *= corr1;
        }

        uint32_t* pw = Ps[warp];
        __syncwarp();
        #pragma unroll
        for (int nt = 0; nt < 4; nt++) {
            pw[gid * 36 + nt * 8 + tig * 2    ]  = f2tf(p[nt][0]);
            pw[gid * 36 + nt * 8 + tig * 2 + 1]  = f2tf(p[nt][1]);
            pw[(gid + 8) * 36 + nt * 8 + tig * 2    ] = f2tf(p[nt][2]);
            pw[(gid + 8) * 36 + nt * 8 + tig * 2 + 1] = f2tf(p[nt][3]);
        }
        __syncwarp();

        #pragma unroll
        for (int ks = 0; ks < 4; ks++) {
            uint32_t af[4];
            af[0] = pw[gid * 36 + ks * 8 + tig];
            af[1] = pw[(gid + 8) * 36 + ks * 8 + tig];
            af[2] = pw[gid * 36 + ks * 8 + tig + 4];
            af[3] = pw[(gid + 8) * 36 + ks * 8 + tig + 4];
            #pragma unroll
            for (int nt = 0; nt < 4; nt++) {
                uint32_t b0 = Vs[(ks * 8 + tig) * 40 + nt * 8 + gid];
                uint32_t b1 = Vs[(ks * 8 + tig + 4) * 40 + nt * 8 + gid];
                mma_tf32(oacc[nt], af, b0, b1);
            }
        }
        m0 = mn0; m1 = mn1;
    }

    float inv0 = (l0 > 0.f) ? 1.f / l0 : 0.f;
    float inv1 = (l1 > 0.f) ? 1.f / l1 : 0.f;
    #pragma unroll
    for (int nt = 0; nt < 4; nt++) {
        int col = h * 32 + nt * 8 + tig * 2;
        if (i0 < NTOK) {
            float2 o = make_float2(ftrunc_tf(oacc[nt][0] * inv0),
                                   ftrunc_tf(oacc[nt][1] * inv0));
            *(float2*)&g_attn[((size_t)b * NTOK + i0) * DIM + col] = o;
        }
        if (i1 < NTOK) {
            float2 o = make_float2(ftrunc_tf(oacc[nt][2] * inv1),
                                   ftrunc_tf(oacc[nt][3] * inv1));
            *(float2*)&g_attn[((size_t)b * NTOK + i1) * DIM + col] = o;
        }
    }
}

// ---------------- host orchestration ---------------------------------------
static inline dim3 gg(int M, int Nn) { return dim3(Nn / 128, (M + 63) / 64); }

extern "C" void kernel_launch(void* const* d_in, const int* in_sizes, int n_in,
                              void* d_out, int out_size) {
    const float* x      = (const float*)d_in[0];
    const float* pos    = (const float*)d_in[1];
    const float* spt_w  = (const float*)d_in[2];
    const float* spt_b  = (const float*)d_in[3];
    const float* ln1_w  = (const float*)d_in[4];
    const float* ln1_b  = (const float*)d_in[5];
    const float* scale  = (const float*)d_in[6];
    const float* wqkv   = (const float*)d_in[7];
    const float* wout   = (const float*)d_in[8];
    const float* bout   = (const float*)d_in[9];
    const float* ln2_w  = (const float*)d_in[10];
    const float* ln2_b  = (const float*)d_in[11];
    const float* ff1_w  = (const float*)d_in[12];
    const float* ff1_b  = (const float*)d_in[13];
    const float* ff2_w  = (const float*)d_in[14];
    const float* ff2_b  = (const float*)d_in[15];
    const float* pix_w  = (const float*)d_in[16];
    const float* pix_b  = (const float*)d_in[17];

    float *t, *qkv, *attn, *ff, *wtf, *lnS, *lnB;
    cudaGetSymbolAddress((void**)&t,    g_t);
    cudaGetSymbolAddress((void**)&qkv,  g_qkv);
    cudaGetSymbolAddress((void**)&attn, g_attn);
    cudaGetSymbolAddress((void**)&ff,   g_ff);
    cudaGetSymbolAddress((void**)&wtf,  g_wtf);
    cudaGetSymbolAddress((void**)&lnS,  g_lnS);
    cudaGetSymbolAddress((void**)&lnB,  g_lnB);

    cudaFuncSetAttribute(gemm_tc<2, 0, true,  true,  true,  true,  true,  false, false>, cudaFuncAttributeMaxDynamicSharedMemorySize, GEMM_SMEM);
    cudaFuncSetAttribute(gemm_tc<2, 0, true,  false, false, false, false, true,  false>, cudaFuncAttributeMaxDynamicSharedMemorySize, GEMM_SMEM);
    cudaFuncSetAttribute(gemm_tc<3, 0, false, false, false, false, false, false, true >, cudaFuncAttributeMaxDynamicSharedMemorySize, GEMM_SMEM);
    cudaFuncSetAttribute(gemm_tc<3, 0, true,  true,  false, true,  false, false, false>, cudaFuncAttributeMaxDynamicSharedMemorySize, GEMM_SMEM);
    cudaFuncSetAttribute(gemm_tc<3, 1, true,  false, false, true,  false, false, true >, cudaFuncAttributeMaxDynamicSharedMemorySize, GEMM_SMEM);

    convert_w<<<(W_TOTAL / 4 + 255) / 256, 256>>>(spt_w, wqkv, wout, ff1_w, ff2_w, pix_w,
                                                  ln1_w, ln2_w);
    colsum_kernel<<<(3 * LNC_PER + 7) / 8, 256>>>(wqkv, ff1_w, ln1_b, ln2_b);

    // spt projection with fused tokenize gather + pos residual (t truncated)
    gemm_tc<2, 0, true, true, true, true, true, false, false><<<gg(MTOK, DIM), 256, GEMM_SMEM>>>(
        x, wtf + W_SPT_OFF, spt_b, pos, t, nullptr, nullptr, MTOK, DIM, 1280);

    for (int d = 0; d < 3; d++) {
        // qkv GEMM with fused LN1 (reads t directly)
        gemm_tc<3, 0, false, false, false, false, false, false, true><<<gg(MTOK, 768), 256, GEMM_SMEM>>>(
            t, wtf + W_QKV_OFF + (size_t)d * 768 * DIM, nullptr, nullptr, qkv,
            lnS + d * LNC_PER, lnB + d * LNC_PER, MTOK, 768, DIM);
        {
            dim3 grid((NTOK + 127) / 128, BATCH * NHEADS);
            attn_mma<<<grid, 256>>>(scale + d * NHEADS);
        }
        gemm_tc<3, 0, true, true, false, true, false, false, false><<<gg(MTOK, DIM), 256, GEMM_SMEM>>>(
            attn, wtf + W_WOUT_OFF + (size_t)d * DIM * DIM, bout + d * DIM, t, t,
            nullptr, nullptr, MTOK, DIM, DIM);
        // ff1 GEMM with fused LN2 + bias + GELU
        gemm_tc<3, 1, true, false, false, true, false, false, true><<<gg(MTOK, 1024), 256, GEMM_SMEM>>>(
            t, wtf + W_FF1_OFF + (size_t)d * 1024 * DIM, ff1_b + d * 1024, nullptr, ff,
            lnS + d * LNC_PER + 768, lnB + d * LNC_PER + 768, MTOK, 1024, DIM);
        gemm_tc<3, 0, true, true, false, true, false, false, false><<<gg(MTOK, DIM), 256, GEMM_SMEM>>>(
            ff, wtf + W_FF2_OFF + (size_t)d * DIM * 1024, ff2_b + d * DIM, t, t,
            nullptr, nullptr, MTOK, DIM, 1024);
    }

    // pix projection with fused untokenize + crop (writes d_out directly)
    gemm_tc<2, 0, true, false, false, false, false, true, false><<<gg(MTOK, DIM), 256, GEMM_SMEM>>>(
        t, wtf + W_PIX_OFF, pix_b, nullptr, (float*)d_out, nullptr, nullptr, MTOK, DIM, DIM);
}

// round 15
// speedup vs baseline: 1.0150x; 1.0150x over previous
#include <cuda_runtime.h>
#include <math.h>
#include <stdint.h>

#define IMGS   457
#define HPAD   464
#define HP     29
#define NTOK   841
#define BATCH  8
#define DIM    256
#define MTOK   (BATCH*NTOK)   // 6728
#define NHEADS 8
#define DH     32

// ---------------- scratch (device globals; no allocations) ----------------
__device__ float g_t   [MTOK*DIM];
__device__ float g_qkv [MTOK*768];
__device__ float g_attn[MTOK*DIM];
__device__ float g_ff  [MTOK*1024];
__device__ float g_lnA [MTOK];   // rstd per row
__device__ float g_lnC [MTOK];   // -mean*rstd per row

// pre-truncated (tf32) weights, with LN gamma folded into qkv/ff1
#define W_SPT_OFF  0
#define W_SPT_SZ   (256*1280)
#define W_QKV_OFF  (W_SPT_OFF+W_SPT_SZ)
#define W_QKV_SZ   (3*768*256)
#define W_WOUT_OFF (W_QKV_OFF+W_QKV_SZ)
#define W_WOUT_SZ  (3*256*256)
#define W_FF1_OFF  (W_WOUT_OFF+W_WOUT_SZ)
#define W_FF1_SZ   (3*1024*256)
#define W_FF2_OFF  (W_FF1_OFF+W_FF1_SZ)
#define W_FF2_SZ   (3*256*1024)
#define W_PIX_OFF  (W_FF2_OFF+W_FF2_SZ)
#define W_PIX_SZ   (256*256)
#define W_TOTAL    (W_PIX_OFF+W_PIX_SZ)
__device__ float g_wtf[W_TOTAL];

// per-layer LN column terms: [layer][ qkv 768 | ff1 1024 ]
#define LNC_PER 1792
__device__ float g_lnS[3*LNC_PER];
__device__ float g_lnB[3*LNC_PER];

__device__ __forceinline__ uint32_t f2tf(float f) {
    uint32_t r;
    asm("cvt.rna.tf32.f32 %0, %1;" : "=r"(r) : "f"(f));
    return r;
}
__device__ __forceinline__ float ftrunc_tf(float f) { return __uint_as_float(f2tf(f)); }

// ---------- weight conversion: tf32 truncate + fold LN gamma --------------
__global__ void convert_w(const float* __restrict__ spt, const float* __restrict__ qkv,
                          const float* __restrict__ wo, const float* __restrict__ f1,
                          const float* __restrict__ f2w, const float* __restrict__ px,
                          const float* __restrict__ ln1w, const float* __restrict__ ln2w) {
    int i4 = blockIdx.x * 256 + threadIdx.x;
    if (i4 >= W_TOTAL / 4) return;
    int i = i4 * 4;
    const float* src; int off;
    if      (i < W_QKV_OFF)  { src = spt; off = 0; }
    else if (i < W_WOUT_OFF) { src = qkv; off = W_QKV_OFF; }
    else if (i < W_FF1_OFF)  { src = wo;  off = W_WOUT_OFF; }
    else if (i < W_FF2_OFF)  { src = f1;  off = W_FF1_OFF; }
    else if (i < W_PIX_OFF)  { src = f2w; off = W_FF2_OFF; }
    else                     { src = px;  off = W_PIX_OFF; }
    float4 v = *(const float4*)(src + (i - off));
    if (i >= W_QKV_OFF && i < W_WOUT_OFF) {
        int rel = i - W_QKV_OFF;
        int d = rel / (768 * 256);
        int k = rel & 255;
        float4 g = *(const float4*)(ln1w + d * 256 + k);
        v.x *= g.x; v.y *= g.y; v.z *= g.z; v.w *= g.w;
    } else if (i >= W_FF1_OFF && i < W_FF2_OFF) {
        int rel = i - W_FF1_OFF;
        int d = rel / (1024 * 256);
        int k = rel & 255;
        float4 g = *(const float4*)(ln2w + d * 256 + k);
        v.x *= g.x; v.y *= g.y; v.z *= g.z; v.w *= g.w;
    }
    v.x = ftrunc_tf(v.x); v.y = ftrunc_tf(v.y);
    v.z = ftrunc_tf(v.z); v.w = ftrunc_tf(v.w);
    *(float4*)&g_wtf[i] = v;
}

// ---------- colsum: S[n] = sum_k W'[n,k];  B2[n] = sum_k W[n,k]*beta[k] ---
__global__ void colsum_kernel(const float* __restrict__ wqkv, const float* __restrict__ f1w,
                              const float* __restrict__ ln1b, const float* __restrict__ ln2b) {
    int n = blockIdx.x * 8 + (threadIdx.x >> 5);
    if (n >= 3 * LNC_PER) return;
    int d = n / LNC_PER, r = n % LNC_PER;
    const float* wt; const float* worig; const float* bln;
    if (r < 768) {
        wt = g_wtf + W_QKV_OFF + (size_t)d * 768 * 256 + (size_t)r * 256;
        worig = wqkv + (size_t)d * 768 * 256 + (size_t)r * 256;
        bln = ln1b + d * 256;
    } else {
        int rr = r - 768;
        wt = g_wtf + W_FF1_OFF + (size_t)d * 1024 * 256 + (size_t)rr * 256;
        worig = f1w + (size_t)d * 1024 * 256 + (size_t)rr * 256;
        bln = ln2b + d * 256;
    }
    int lane = threadIdx.x & 31;
    float s = 0.f, b = 0.f;
    #pragma unroll
    for (int k = lane; k < 256; k += 32) { s += wt[k]; b += worig[k] * bln[k]; }
    #pragma unroll
    for (int o = 16; o; o >>= 1) {
        s += __shfl_xor_sync(0xffffffffu, s, o);
        b += __shfl_xor_sync(0xffffffffu, b, o);
    }
    if (lane == 0) { g_lnS[n] = s; g_lnB[n] = b; }
}

// ---------- row stats: a[m] = rstd, c[m] = -mean*rstd ---------------------
__global__ void stats_kernel(const float* __restrict__ in) {
    int warp = threadIdx.x / 32, lane = threadIdx.x % 32;
    int m = blockIdx.x * 8 + warp;
    if (m >= MTOK) return;
    const float* row = in + (size_t)m * DIM + lane * 8;
    float4 a = *(const float4*)row;
    float4 c = *(const float4*)(row + 4);
    float s  = a.x + a.y + a.z + a.w + c.x + c.y + c.z + c.w;
    float s2 = a.x*a.x + a.y*a.y + a.z*a.z + a.w*a.w
             + c.x*c.x + c.y*c.y + c.z*c.z + c.w*c.w;
    #pragma unroll
    for (int o = 16; o; o >>= 1) {
        s  += __shfl_xor_sync(0xffffffffu, s,  o);
        s2 += __shfl_xor_sync(0xffffffffu, s2, o);
    }
    if (lane == 0) {
        float mean = s * (1.f / 256.f);
        float var  = s2 * (1.f / 256.f) - mean * mean;
        float rstd = rsqrtf(var + 1e-5f);
        g_lnA[m] = rstd;
        g_lnC[m] = -mean * rstd;
    }
}

// ---------------- tf32 tensor-core GEMM, BM=64, 3-stage cp.async, LDSM ----
__device__ __forceinline__ void mma_tf32(float c[4], const uint32_t a[4],
                                         uint32_t b0, uint32_t b1) {
    asm volatile(
        "mma.sync.aligned.m16n8k8.row.col.f32.tf32.tf32.f32 "
        "{%0,%1,%2,%3}, {%4,%5,%6,%7}, {%8,%9}, {%0,%1,%2,%3};"
        : "+f"(c[0]), "+f"(c[1]), "+f"(c[2]), "+f"(c[3])
        : "r"(a[0]), "r"(a[1]), "r"(a[2]), "r"(a[3]), "r"(b0), "r"(b1));
}
__device__ __forceinline__ float gelu_exact(float v) {
    return 0.5f * v * (1.0f + erff(v * 0.70710678118654752440f));
}
__device__ __forceinline__ void cp16(uint32_t saddr, const float* g, bool pred) {
    asm volatile("cp.async.cg.shared.global [%0], [%1], 16, %2;"
                 :: "r"(saddr), "l"(g), "r"(pred ? 16 : 0));
}
__device__ __forceinline__ void cp4(uint32_t saddr, const float* g, bool pred) {
    asm volatile("cp.async.ca.shared.global [%0], [%1], 4, %2;"
                 :: "r"(saddr), "l"(g), "r"(pred ? 4 : 0));
}
__device__ __forceinline__ void cp_commit() { asm volatile("cp.async.commit_group;"); }
template<int N>
__device__ __forceinline__ void cp_wait() {
    asm volatile("cp.async.wait_group %0;" :: "n"(N));
}
__device__ __forceinline__ int swz(int row, int col) {
    return row * 32 + (col ^ ((row & 7) * 4));
}
__device__ __forceinline__ void ldsm4(uint32_t addr, uint32_t& r0, uint32_t& r1,
                                      uint32_t& r2, uint32_t& r3) {
    asm volatile("ldmatrix.sync.aligned.m8n8.x4.shared.b16 {%0,%1,%2,%3}, [%4];"
                 : "=r"(r0), "=r"(r1), "=r"(r2), "=r"(r3) : "r"(addr));
}

#define GEMM_SMEM (3 * (64 * 32 + 4096) * 4)   // 73728 B

template<int MINB, int ACT, bool HASBIAS, bool HASRES, bool POSMOD, bool TRUNC,
         bool GATHER, bool RESHAPE, bool LNFUSE>
__global__ void __launch_bounds__(256, MINB)
gemm_tc(const float* __restrict__ A, const float* __restrict__ W,
        const float* __restrict__ bias, const float* __restrict__ res,
        float* __restrict__ C, const float* __restrict__ Sarr,
        const float* __restrict__ Barr, int M, int Nn, int K) {
    constexpr int BM = 64;
    constexpr int NWM = 2;
    constexpr int WN  = 32;
    constexpr int NP  = 2;
    constexpr int NT  = 4;
    constexpr int ASTG = BM * 32;

    extern __shared__ float smem[];
    float* As = smem;
    float* Ws = smem + 3 * ASTG;
    const int tid  = threadIdx.x;
    const int wid  = tid >> 5, lane = tid & 31;
    const int wm   = wid % NWM, wn = wid / NWM;
    const int gid  = lane >> 2, tig = lane & 3;
    const int m0   = blockIdx.y * BM, n0 = blockIdx.x * 128;

    const int lrow = tid >> 3;
    const int lc4  = (tid & 7) * 4;

    uint32_t As_base = (uint32_t)__cvta_generic_to_shared(As);
    uint32_t Ws_base = (uint32_t)__cvta_generic_to_shared(Ws);

    const int rowA_in  = (lane & 15);
    const int koffA    = ((lane >> 4) & 1) * 4;
    const int rowB_in  = (lane & 7) + (((lane >> 4) & 1) << 3);
    const int koffB    = ((lane >> 3) & 1) * 4;

    bool grow[2];
    int  gb[2], gpy[2], gpx[2];
    if (GATHER) {
        #pragma unroll
        for (int i = 0; i < 2; i++) {
            int m = m0 + lrow + i * 32;
            grow[i] = m < M;
            int mm = m < M ? m : (M - 1);
            gb[i] = mm / NTOK;
            int n8 = mm - gb[i] * NTOK;
            gpy[i] = n8 / HP;
            gpx[i] = n8 - gpy[i] * HP;
        }
    }

    float acc[2][NT][4] = {};
    const int ktiles = K >> 5;

    auto load_tile = [&](int kt, int buf) {
        if (GATHER) {
            int c  = kt * 32 + lc4;
            int s  = c >> 8;
            int pr = (c >> 4) & 15;
            int pc = c & 15;
            int dy = (s == 0) ? 0 : ((s <= 2) ? -8 : 8);
            int dx = (s == 0) ? 0 : ((s & 1) ? -8 : 8);
            #pragma unroll
            for (int i = 0; i < 2; i++) {
                int row = lrow + i * 32;
                uint32_t sdst = As_base + (buf * ASTG + swz(row, lc4)) * 4;
                int y  = gpy[i] * 16 + pr - dy;
                if (y < 0) y += HPAD; if (y >= HPAD) y -= HPAD;
                int xx = gpx[i] * 16 + pc - dx;
                if (xx < 0) xx += HPAD; if (xx >= HPAD) xx -= HPAD;
                bool yv = grow[i] && (y < IMGS);
                const float* src = A + ((size_t)gb[i] * IMGS + y) * IMGS + xx;
                #pragma unroll
                for (int q = 0; q < 4; q++)
                    cp4(sdst + q * 4, src + q, yv && (xx + q) < IMGS);
            }
        } else {
            const float* Ag = A + (size_t)m0 * K + kt * 32;
            #pragma unroll
            for (int i = 0; i < 2; i++) {
                int row = lrow + i * 32;
                uint32_t s = As_base + (buf * ASTG + swz(row, lc4)) * 4;
                cp16(s, Ag + (size_t)row * K + lc4, (m0 + row) < M);
            }
        }
        const float* Wg = W + (size_t)n0 * K + kt * 32;
        #pragma unroll
        for (int i = 0; i < 4; i++) {
            int row = lrow + i * 32;
            uint32_t s = Ws_base + (buf * 4096 + swz(row, lc4)) * 4;
            cp16(s, Wg + (size_t)row * K + lc4, true);
        }
    };

    load_tile(0, 0);
    cp_commit();
    if (ktiles > 1) { load_tile(1, 1); cp_commit(); }

    for (int kt = 0; kt < ktiles; kt++) {
        if (kt + 2 < ktiles) {
            load_tile(kt + 2, (kt + 2) % 3);
            cp_commit();
            cp_wait<2>();
        } else if (kt + 1 < ktiles) {
            cp_wait<1>();
        } else {
            cp_wait<0>();
        }
        __syncthreads();

        const uint32_t as_b = As_base + ((kt % 3) * ASTG) * 4;
        const uint32_t ws_b = Ws_base + ((kt % 3) * 4096) * 4;
        #pragma unroll
        for (int ks = 0; ks < 32; ks += 8) {
            uint32_t af[2][4];
            #pragma unroll
            for (int mt = 0; mt < 2; mt++) {
                int row = wm * 32 + mt * 16 + rowA_in;
                int col = ks + koffA;
                uint32_t addr = as_b + (uint32_t)swz(row, col) * 4;
                ldsm4(addr, af[mt][0], af[mt][1], af[mt][2], af[mt][3]);
            }
            #pragma unroll
            for (int np = 0; np < NP; np++) {
                int row = wn * WN + np * 16 + rowB_in;
                int col = ks + koffB;
                uint32_t addr = ws_b + (uint32_t)swz(row, col) * 4;
                uint32_t b0a, b1a, b0b, b1b;
                ldsm4(addr, b0a, b1a, b0b, b1b);
                mma_tf32(acc[0][2 * np    ], af[0], b0a, b1a);
                mma_tf32(acc[1][2 * np    ], af[1], b0a, b1a);
                mma_tf32(acc[0][2 * np + 1], af[0], b0b, b1b);
                mma_tf32(acc[1][2 * np + 1], af[1], b0b, b1b);
            }
        }
        __syncthreads();
    }

    #pragma unroll
    for (int mt = 0; mt < 2; mt++) {
        #pragma unroll
        for (int half = 0; half < 2; half++) {
            int m = m0 + wm * 32 + mt * 16 + gid + half * 8;
            if (m >= M) continue;
            int mres = POSMOD ? (m % NTOK) : m;
            float la = 0.f, lc = 0.f;
            if (LNFUSE) { la = g_lnA[m]; lc = g_lnC[m]; }
            int ob = 0, opy = 0, opx = 0;
            if (RESHAPE) {
                ob = m / NTOK;
                int n8 = m - ob * NTOK;
                opy = n8 / HP;
                opx = n8 - opy * HP;
            }
            #pragma unroll
            for (int nt = 0; nt < NT; nt++) {
                int n = n0 + wn * WN + nt * 8 + tig * 2;
                float v0 = acc[mt][nt][half * 2 + 0];
                float v1 = acc[mt][nt][half * 2 + 1];
                if (LNFUSE) {
                    float2 S = *(const float2*)&Sarr[n];
                    float2 B = *(const float2*)&Barr[n];
                    v0 = fmaf(la, v0, fmaf(lc, S.x, B.x));
                    v1 = fmaf(la, v1, fmaf(lc, S.y, B.y));
                }
                if (HASBIAS) { v0 += bias[n]; v1 += bias[n + 1]; }
                if (ACT == 1) { v0 = gelu_exact(v0); v1 = gelu_exact(v1); }
                if (HASRES) {
                    float2 r = *(const float2*)&res[(size_t)mres * Nn + n];
                    v0 += r.x; v1 += r.y;
                }
                if (TRUNC) { v0 = ftrunc_tf(v0); v1 = ftrunc_tf(v1); }
                if (RESHAPE) {
                    int y  = opy * 16 + (n >> 4);
                    int xc = opx * 16 + (n & 15);
                    if (y < IMGS) {
                        float* orow = C + ((size_t)ob * IMGS + y) * IMGS;
                        if (xc < IMGS)     orow[xc]     = v0;
                        if (xc + 1 < IMGS) orow[xc + 1] = v1;
                    }
                } else {
                    *(float2*)&C[(size_t)m * Nn + n] = make_float2(v0, v1);
                }
            }
        }
    }
}

// ---------------- MMA flash attention, q-tile 128, 8 warps ----------------
__global__ void __launch_bounds__(256)
attn_mma(const float* __restrict__ scale_d) {
    __shared__ uint32_t Ks[32 * 36];
    __shared__ uint32_t Vs[32 * 40];
    __shared__ uint32_t Ps[8][16 * 36];

    const int bh = blockIdx.y;
    const int b = bh >> 3, h = bh & 7;
    const int tid = threadIdx.x;
    const int warp = tid >> 5, lane = tid & 31;
    const int gid = lane >> 2, tig = lane & 3;
    const int q0 = (gridDim.x - 1 - blockIdx.x) * 128;
    const float* base = g_qkv + (size_t)b * NTOK * 768;
    const float sc = scale_d[h];

    const int i0 = q0 + warp * 16 + gid;
    const int i1 = i0 + 8;

    uint32_t qf[4][4];
    #pragma unroll
    for (int ks = 0; ks < 4; ks++) {
        int c = h * 32 + ks * 8 + tig;
        float v00 = 0.f, v10 = 0.f, v01 = 0.f, v11 = 0.f;
        if (i0 < NTOK) { v00 = base[(size_t)i0 * 768 + c] * sc;
                         v01 = base[(size_t)i0 * 768 + c + 4] * sc; }
        if (i1 < NTOK) { v10 = base[(size_t)i1 * 768 + c] * sc;
                         v11 = base[(size_t)i1 * 768 + c + 4] * sc; }
        qf[ks][0] = f2tf(v00); qf[ks][1] = f2tf(v10);
        qf[ks][2] = f2tf(v01); qf[ks][3] = f2tf(v11);
    }

    float m0 = -1e30f, m1 = -1e30f, l0 = 0.f, l1 = 0.f;
    float oacc[4][4] = {};

    const int jmax = min(q0 + 127, NTOK - 1);
    for (int j0 = 0; j0 < jmax; j0 += 32) {
        __syncthreads();
        {
            int r  = tid >> 3;
            int c4 = (tid & 7) * 4;
            int j  = j0 + r;
            if (j < NTOK) {
                const float* kp = base + (size_t)j * 768 + 256 + h * 32 + c4;
                const float* vp = base + (size_t)j * 768 + 512 + h * 32 + c4;
                float4 ka = *(const float4*)kp;
                Ks[r * 36 + c4 + 0] = f2tf(ka.x); Ks[r * 36 + c4 + 1] = f2tf(ka.y);
                Ks[r * 36 + c4 + 2] = f2tf(ka.z); Ks[r * 36 + c4 + 3] = f2tf(ka.w);
                float4 va = *(const float4*)vp;
                Vs[r * 40 + c4 + 0] = f2tf(va.x); Vs[r * 40 + c4 + 1] = f2tf(va.y);
                Vs[r * 40 + c4 + 2] = f2tf(va.z); Vs[r * 40 + c4 + 3] = f2tf(va.w);
            } else {
                #pragma unroll
                for (int q = 0; q < 4; q++) {
                    Ks[r * 36 + c4 + q] = 0;
                    Vs[r * 40 + c4 + q] = 0;
                }
            }
        }
        __syncthreads();

        float s[4][4] = {};
        #pragma unroll
        for (int ks = 0; ks < 4; ks++) {
            #pragma unroll
            for (int nt = 0; nt < 4; nt++) {
                uint32_t b0 = Ks[(nt * 8 + gid) * 36 + ks * 8 + tig];
                uint32_t b1 = Ks[(nt * 8 + gid) * 36 + ks * 8 + tig + 4];
                mma_tf32(s[nt], qf[ks], b0, b1);
            }
        }

        float rm0 = -1e30f, rm1 = -1e30f;
        #pragma unroll
        for (int nt = 0; nt < 4; nt++) {
            int jc = j0 + nt * 8 + tig * 2;
            if (jc     >= i0) s[nt][0] = -1e30f;
            if (jc + 1 >= i0) s[nt][1] = -1e30f;
            if (jc     >= i1) s[nt][2] = -1e30f;
            if (jc + 1 >= i1) s[nt][3] = -1e30f;
            rm0 = fmaxf(rm0, fmaxf(s[nt][0], s[nt][1]));
            rm1 = fmaxf(rm1, fmaxf(s[nt][2], s[nt][3]));
        }
        rm0 = fmaxf(rm0, __shfl_xor_sync(0xffffffffu, rm0, 1));
        rm0 = fmaxf(rm0, __shfl_xor_sync(0xffffffffu, rm0, 2));
        rm1 = fmaxf(rm1, __shfl_xor_sync(0xffffffffu, rm1, 1));
        rm1 = fmaxf(rm1, __shfl_xor_sync(0xffffffffu, rm1, 2));
        float mn0 = fmaxf(m0, rm0), mn1 = fmaxf(m1, rm1);
        float corr0 = __expf(m0 - mn0), corr1 = __expf(m1 - mn1);

        float p[4][4];
        float ps0 = 0.f, ps1 = 0.f;
        #pragma unroll
        for (int nt = 0; nt < 4; nt++) {
            p[nt][0] = (s[nt][0] < -1e29f) ? 0.f : __expf(s[nt][0] - mn0);
            p[nt][1] = (s[nt][1] < -1e29f) ? 0.f : __expf(s[nt][1] - mn0);
            p[nt][2] = (s[nt][2] < -1e29f) ? 0.f : __expf(s[nt][2] - mn1);
            p[nt][3] = (s[nt][3] < -1e29f) ? 0.f : __expf(s[nt][3] - mn1);
            ps0 += p[nt][0] + p[nt][1];
            ps1 += p[nt][2] + p[nt][3];
        }
        ps0 += __shfl_xor_sync(0xffffffffu, ps0, 1);
        ps0 += __shfl_xor_sync(0xffffffffu, ps0, 2);
        ps1 += __shfl_xor_sync(0xffffffffu, ps1, 1);
        ps1 += __shfl_xor_sync(0xffffffffu, ps1, 2);
        l0 = l0 * corr0 + ps0;
        l1 = l1 * corr1 + ps1;
        #pragma unroll
        for (int nt = 0; nt < 4; nt++) {
            oacc[nt][0] *= corr0; oacc[nt][1] *= corr0;
            oacc[nt][2] *= corr1; oacc[nt][3] *= corr1;
        }

        uint32_t* pw = Ps[warp];
        __syncwarp();
        #pragma unroll
        for (int nt = 0; nt < 4; nt++) {
            pw[gid * 36 + nt * 8 + tig * 2    ]  = f2tf(p[nt][0]);
            pw[gid * 36 + nt * 8 + tig * 2 + 1]  = f2tf(p[nt][1]);
            pw[(gid + 8) * 36 + nt * 8 + tig * 2    ] = f2tf(p[nt][2]);
            pw[(gid + 8) * 36 + nt * 8 + tig * 2 + 1] = f2tf(p[nt][3]);
        }
        __syncwarp();

        #pragma unroll
        for (int ks = 0; ks < 4; ks++) {
            uint32_t af[4];
            af[0] = pw[gid * 36 + ks * 8 + tig];
            af[1] = pw[(gid + 8) * 36 + ks * 8 + tig];
            af[2] = pw[gid * 36 + ks * 8 + tig + 4];
            af[3] = pw[(gid + 8) * 36 + ks * 8 + tig + 4];
            #pragma unroll
            for (int nt = 0; nt < 4; nt++) {
                uint32_t b0 = Vs[(ks * 8 + tig) * 40 + nt * 8 + gid];
                uint32_t b1 = Vs[(ks * 8 + tig + 4) * 40 + nt * 8 + gid];
                mma_tf32(oacc[nt], af, b0, b1);
            }
        }
        m0 = mn0; m1 = mn1;
    }

    float inv0 = (l0 > 0.f) ? 1.f / l0 : 0.f;
    float inv1 = (l1 > 0.f) ? 1.f / l1 : 0.f;
    #pragma unroll
    for (int nt = 0; nt < 4; nt++) {
        int col = h * 32 + nt * 8 + tig * 2;
        if (i0 < NTOK) {
            float2 o = make_float2(ftrunc_tf(oacc[nt][0] * inv0),
                                   ftrunc_tf(oacc[nt][1] * inv0));
            *(float2*)&g_attn[((size_t)b * NTOK + i0) * DIM + col] = o;
        }
        if (i1 < NTOK) {
            float2 o = make_float2(ftrunc_tf(oacc[nt][2] * inv1),
                                   ftrunc_tf(oacc[nt][3] * inv1));
            *(float2*)&g_attn[((size_t)b * NTOK + i1) * DIM + col] = o;
        }
    }
}

// ---------------- host orchestration ---------------------------------------
static inline dim3 gg(int M, int Nn) { return dim3(Nn / 128, (M + 63) / 64); }

extern "C" void kernel_launch(void* const* d_in, const int* in_sizes, int n_in,
                              void* d_out, int out_size) {
    const float* x      = (const float*)d_in[0];
    const float* pos    = (const float*)d_in[1];
    const float* spt_w  = (const float*)d_in[2];
    const float* spt_b  = (const float*)d_in[3];
    const float* ln1_w  = (const float*)d_in[4];
    const float* ln1_b  = (const float*)d_in[5];
    const float* scale  = (const float*)d_in[6];
    const float* wqkv   = (const float*)d_in[7];
    const float* wout   = (const float*)d_in[8];
    const float* bout   = (const float*)d_in[9];
    const float* ln2_w  = (const float*)d_in[10];
    const float* ln2_b  = (const float*)d_in[11];
    const float* ff1_w  = (const float*)d_in[12];
    const float* ff1_b  = (const float*)d_in[13];
    const float* ff2_w  = (const float*)d_in[14];
    const float* ff2_b  = (const float*)d_in[15];
    const float* pix_w  = (const float*)d_in[16];
    const float* pix_b  = (const float*)d_in[17];

    float *t, *qkv, *attn, *ff, *wtf, *lnS, *lnB;
    cudaGetSymbolAddress((void**)&t,    g_t);
    cudaGetSymbolAddress((void**)&qkv,  g_qkv);
    cudaGetSymbolAddress((void**)&attn, g_attn);
    cudaGetSymbolAddress((void**)&ff,   g_ff);
    cudaGetSymbolAddress((void**)&wtf,  g_wtf);
    cudaGetSymbolAddress((void**)&lnS,  g_lnS);
    cudaGetSymbolAddress((void**)&lnB,  g_lnB);

    cudaFuncSetAttribute(gemm_tc<2, 0, true,  true,  true,  true,  true,  false, false>, cudaFuncAttributeMaxDynamicSharedMemorySize, GEMM_SMEM);
    cudaFuncSetAttribute(gemm_tc<2, 0, true,  false, false, false, false, true,  false>, cudaFuncAttributeMaxDynamicSharedMemorySize, GEMM_SMEM);
    cudaFuncSetAttribute(gemm_tc<3, 0, false, false, false, false, false, false, true >, cudaFuncAttributeMaxDynamicSharedMemorySize, GEMM_SMEM);
    cudaFuncSetAttribute(gemm_tc<3, 0, true,  true,  false, true,  false, false, false>, cudaFuncAttributeMaxDynamicSharedMemorySize, GEMM_SMEM);
    cudaFuncSetAttribute(gemm_tc<3, 1, true,  false, false, true,  false, false, true >, cudaFuncAttributeMaxDynamicSharedMemorySize, GEMM_SMEM);

    convert_w<<<(W_TOTAL / 4 + 255) / 256, 256>>>(spt_w, wqkv, wout, ff1_w, ff2_w, pix_w,
                                                  ln1_w, ln2_w);
    colsum_kernel<<<(3 * LNC_PER + 7) / 8, 256>>>(wqkv, ff1_w, ln1_b, ln2_b);

    // spt projection with fused tokenize gather + pos residual (t truncated)
    gemm_tc<2, 0, true, true, true, true, true, false, false><<<gg(MTOK, DIM), 256, GEMM_SMEM>>>(
        x, wtf + W_SPT_OFF, spt_b, pos, t, nullptr, nullptr, MTOK, DIM, 1280);

    const int ST_BLOCKS = (MTOK + 7) / 8;
    for (int d = 0; d < 3; d++) {
        // LN1 stats then qkv GEMM with epilogue LN
        stats_kernel<<<ST_BLOCKS, 256>>>(t);
        gemm_tc<3, 0, false, false, false, false, false, false, true><<<gg(MTOK, 768), 256, GEMM_SMEM>>>(
            t, wtf + W_QKV_OFF + (size_t)d * 768 * DIM, nullptr, nullptr, qkv,
            lnS + d * LNC_PER, lnB + d * LNC_PER, MTOK, 768, DIM);
        {
            dim3 grid((NTOK + 127) / 128, BATCH * NHEADS);
            attn_mma<<<grid, 256>>>(scale + d * NHEADS);
        }
        gemm_tc<3, 0, true, true, false, true, false, false, false><<<gg(MTOK, DIM), 256, GEMM_SMEM>>>(
            attn, wtf + W_WOUT_OFF + (size_t)d * DIM * DIM, bout + d * DIM, t, t,
            nullptr, nullptr, MTOK, DIM, DIM);
        // LN2 stats then ff1 GEMM with epilogue LN + bias + GELU
        stats_kernel<<<ST_BLOCKS, 256>>>(t);
        gemm_tc<3, 1, true, false, false, true, false, false, true><<<gg(MTOK, 1024), 256, GEMM_SMEM>>>(
            t, wtf + W_FF1_OFF + (size_t)d * 1024 * DIM, ff1_b + d * 1024, nullptr, ff,
            lnS + d * LNC_PER + 768, lnB + d * LNC_PER + 768, MTOK, 1024, DIM);
        gemm_tc<3, 0, true, true, false, true, false, false, false><<<gg(MTOK, DIM), 256, GEMM_SMEM>>>(
            ff, wtf + W_FF2_OFF + (size_t)d * DIM * 1024, ff2_b + d * DIM, t, t,
            nullptr, nullptr, MTOK, DIM, 1024);
    }

    // pix projection with fused untokenize + crop (writes d_out directly)
    gemm_tc<2, 0, true, false, false, false, false, true, false><<<gg(MTOK, DIM), 256, GEMM_SMEM>>>(
        t, wtf + W_PIX_OFF, pix_b, nullptr, (float*)d_out, nullptr, nullptr, MTOK, DIM, DIM);
}

// round 16
// speedup vs baseline: 1.0500x; 1.0344x over previous
#include <cuda_runtime.h>
#include <math.h>
#include <stdint.h>

#define IMGS   457
#define HPAD   464
#define HP     29
#define NTOK   841
#define BATCH  8
#define DIM    256
#define MTOK   (BATCH*NTOK)   // 6728
#define NHEADS 8
#define DH     32

// ---------------- scratch (device globals; no allocations) ----------------
__device__ float g_t   [MTOK*DIM];
__device__ float g_qkv [MTOK*768];
__device__ float g_attn[MTOK*DIM];
__device__ float g_ff  [MTOK*1024];
__device__ float2 g_part[2*MTOK];   // per-CTA-x partial (sum, sumsq) of t rows

// pre-truncated (tf32) weights, with LN gamma folded into qkv/ff1
#define W_SPT_OFF  0
#define W_SPT_SZ   (256*1280)
#define W_QKV_OFF  (W_SPT_OFF+W_SPT_SZ)
#define W_QKV_SZ   (3*768*256)
#define W_WOUT_OFF (W_QKV_OFF+W_QKV_SZ)
#define W_WOUT_SZ  (3*256*256)
#define W_FF1_OFF  (W_WOUT_OFF+W_WOUT_SZ)
#define W_FF1_SZ   (3*1024*256)
#define W_FF2_OFF  (W_FF1_OFF+W_FF1_SZ)
#define W_FF2_SZ   (3*256*1024)
#define W_PIX_OFF  (W_FF2_OFF+W_FF2_SZ)
#define W_PIX_SZ   (256*256)
#define W_TOTAL    (W_PIX_OFF+W_PIX_SZ)
__device__ float g_wtf[W_TOTAL];

// per-layer LN column terms: [layer][ qkv 768 | ff1 1024 ]
#define LNC_PER 1792
__device__ float g_lnS[3*LNC_PER];
__device__ float g_lnB[3*LNC_PER];

__device__ __forceinline__ uint32_t f2tf(float f) {
    uint32_t r;
    asm("cvt.rna.tf32.f32 %0, %1;" : "=r"(r) : "f"(f));
    return r;
}
__device__ __forceinline__ float ftrunc_tf(float f) { return __uint_as_float(f2tf(f)); }

// ---------- weight conversion: tf32 truncate + fold LN gamma --------------
__global__ void convert_w(const float* __restrict__ spt, const float* __restrict__ qkv,
                          const float* __restrict__ wo, const float* __restrict__ f1,
                          const float* __restrict__ f2w, const float* __restrict__ px,
                          const float* __restrict__ ln1w, const float* __restrict__ ln2w) {
    int i4 = blockIdx.x * 256 + threadIdx.x;
    if (i4 >= W_TOTAL / 4) return;
    int i = i4 * 4;
    const float* src; int off;
    if      (i < W_QKV_OFF)  { src = spt; off = 0; }
    else if (i < W_WOUT_OFF) { src = qkv; off = W_QKV_OFF; }
    else if (i < W_FF1_OFF)  { src = wo;  off = W_WOUT_OFF; }
    else if (i < W_FF2_OFF)  { src = f1;  off = W_FF1_OFF; }
    else if (i < W_PIX_OFF)  { src = f2w; off = W_FF2_OFF; }
    else                     { src = px;  off = W_PIX_OFF; }
    float4 v = *(const float4*)(src + (i - off));
    if (i >= W_QKV_OFF && i < W_WOUT_OFF) {
        int rel = i - W_QKV_OFF;
        int d = rel / (768 * 256);
        int k = rel & 255;
        float4 g = *(const float4*)(ln1w + d * 256 + k);
        v.x *= g.x; v.y *= g.y; v.z *= g.z; v.w *= g.w;
    } else if (i >= W_FF1_OFF && i < W_FF2_OFF) {
        int rel = i - W_FF1_OFF;
        int d = rel / (1024 * 256);
        int k = rel & 255;
        float4 g = *(const float4*)(ln2w + d * 256 + k);
        v.x *= g.x; v.y *= g.y; v.z *= g.z; v.w *= g.w;
    }
    v.x = ftrunc_tf(v.x); v.y = ftrunc_tf(v.y);
    v.z = ftrunc_tf(v.z); v.w = ftrunc_tf(v.w);
    *(float4*)&g_wtf[i] = v;
}

// ---------- colsum: S[n] = sum_k W'[n,k];  B2[n] = sum_k W[n,k]*beta[k] ---
__global__ void colsum_kernel(const float* __restrict__ wqkv, const float* __restrict__ f1w,
                              const float* __restrict__ ln1b, const float* __restrict__ ln2b) {
    int n = blockIdx.x * 8 + (threadIdx.x >> 5);
    if (n >= 3 * LNC_PER) return;
    int d = n / LNC_PER, r = n % LNC_PER;
    const float* wt; const float* worig; const float* bln;
    if (r < 768) {
        wt = g_wtf + W_QKV_OFF + (size_t)d * 768 * 256 + (size_t)r * 256;
        worig = wqkv + (size_t)d * 768 * 256 + (size_t)r * 256;
        bln = ln1b + d * 256;
    } else {
        int rr = r - 768;
        wt = g_wtf + W_FF1_OFF + (size_t)d * 1024 * 256 + (size_t)rr * 256;
        worig = f1w + (size_t)d * 1024 * 256 + (size_t)rr * 256;
        bln = ln2b + d * 256;
    }
    int lane = threadIdx.x & 31;
    float s = 0.f, b = 0.f;
    #pragma unroll
    for (int k = lane; k < 256; k += 32) { s += wt[k]; b += worig[k] * bln[k]; }
    #pragma unroll
    for (int o = 16; o; o >>= 1) {
        s += __shfl_xor_sync(0xffffffffu, s, o);
        b += __shfl_xor_sync(0xffffffffu, b, o);
    }
    if (lane == 0) { g_lnS[n] = s; g_lnB[n] = b; }
}

// ---------------- tf32 tensor-core GEMM, BM=64, 3-stage cp.async, LDSM ----
__device__ __forceinline__ void mma_tf32(float c[4], const uint32_t a[4],
                                         uint32_t b0, uint32_t b1) {
    asm volatile(
        "mma.sync.aligned.m16n8k8.row.col.f32.tf32.tf32.f32 "
        "{%0,%1,%2,%3}, {%4,%5,%6,%7}, {%8,%9}, {%0,%1,%2,%3};"
        : "+f"(c[0]), "+f"(c[1]), "+f"(c[2]), "+f"(c[3])
        : "r"(a[0]), "r"(a[1]), "r"(a[2]), "r"(a[3]), "r"(b0), "r"(b1));
}
__device__ __forceinline__ float gelu_exact(float v) {
    return 0.5f * v * (1.0f + erff(v * 0.70710678118654752440f));
}
__device__ __forceinline__ void cp16(uint32_t saddr, const float* g, bool pred) {
    asm volatile("cp.async.cg.shared.global [%0], [%1], 16, %2;"
                 :: "r"(saddr), "l"(g), "r"(pred ? 16 : 0));
}
__device__ __forceinline__ void cp4(uint32_t saddr, const float* g, bool pred) {
    asm volatile("cp.async.ca.shared.global [%0], [%1], 4, %2;"
                 :: "r"(saddr), "l"(g), "r"(pred ? 4 : 0));
}
__device__ __forceinline__ void cp_commit() { asm volatile("cp.async.commit_group;"); }
template<int N>
__device__ __forceinline__ void cp_wait() {
    asm volatile("cp.async.wait_group %0;" :: "n"(N));
}
__device__ __forceinline__ int swz(int row, int col) {
    return row * 32 + (col ^ ((row & 7) * 4));
}
__device__ __forceinline__ void ldsm4(uint32_t addr, uint32_t& r0, uint32_t& r1,
                                      uint32_t& r2, uint32_t& r3) {
    asm volatile("ldmatrix.sync.aligned.m8n8.x4.shared.b16 {%0,%1,%2,%3}, [%4];"
                 : "=r"(r0), "=r"(r1), "=r"(r2), "=r"(r3) : "r"(addr));
}

#define GEMM_SMEM (3 * (64 * 32 + 4096) * 4)   // 73728 B

template<int MINB, int ACT, bool HASBIAS, bool HASRES, bool POSMOD, bool TRUNC,
         bool GATHER, bool RESHAPE, bool LNFUSE, bool STATS>
__global__ void __launch_bounds__(256, MINB)
gemm_tc(const float* __restrict__ A, const float* __restrict__ W,
        const float* __restrict__ bias, const float* __restrict__ res,
        float* __restrict__ C, const float* __restrict__ Sarr,
        const float* __restrict__ Barr, int M, int Nn, int K) {
    constexpr int BM = 64;
    constexpr int NWM = 2;
    constexpr int WN  = 32;
    constexpr int NP  = 2;
    constexpr int NT  = 4;
    constexpr int ASTG = BM * 32;

    extern __shared__ float smem[];
    float* As = smem;
    float* Ws = smem + 3 * ASTG;
    const int tid  = threadIdx.x;
    const int wid  = tid >> 5, lane = tid & 31;
    const int wm   = wid % NWM, wn = wid / NWM;
    const int gid  = lane >> 2, tig = lane & 3;
    const int m0   = blockIdx.y * BM, n0 = blockIdx.x * 128;

    const int lrow = tid >> 3;
    const int lc4  = (tid & 7) * 4;

    uint32_t As_base = (uint32_t)__cvta_generic_to_shared(As);
    uint32_t Ws_base = (uint32_t)__cvta_generic_to_shared(Ws);

    const int rowA_in  = (lane & 15);
    const int koffA    = ((lane >> 4) & 1) * 4;
    const int rowB_in  = (lane & 7) + (((lane >> 4) & 1) << 3);
    const int koffB    = ((lane >> 3) & 1) * 4;

    bool grow[2];
    int  gb[2], gpy[2], gpx[2];
    if (GATHER) {
        #pragma unroll
        for (int i = 0; i < 2; i++) {
            int m = m0 + lrow + i * 32;
            grow[i] = m < M;
            int mm = m < M ? m : (M - 1);
            gb[i] = mm / NTOK;
            int n8 = mm - gb[i] * NTOK;
            gpy[i] = n8 / HP;
            gpx[i] = n8 - gpy[i] * HP;
        }
    }

    float acc[2][NT][4] = {};
    const int ktiles = K >> 5;

    auto load_tile = [&](int kt, int buf) {
        if (GATHER) {
            int c  = kt * 32 + lc4;
            int s  = c >> 8;
            int pr = (c >> 4) & 15;
            int pc = c & 15;
            int dy = (s == 0) ? 0 : ((s <= 2) ? -8 : 8);
            int dx = (s == 0) ? 0 : ((s & 1) ? -8 : 8);
            #pragma unroll
            for (int i = 0; i < 2; i++) {
                int row = lrow + i * 32;
                uint32_t sdst = As_base + (buf * ASTG + swz(row, lc4)) * 4;
                int y  = gpy[i] * 16 + pr - dy;
                if (y < 0) y += HPAD; if (y >= HPAD) y -= HPAD;
                int xx = gpx[i] * 16 + pc - dx;
                if (xx < 0) xx += HPAD; if (xx >= HPAD) xx -= HPAD;
                bool yv = grow[i] && (y < IMGS);
                const float* src = A + ((size_t)gb[i] * IMGS + y) * IMGS + xx;
                #pragma unroll
                for (int q = 0; q < 4; q++)
                    cp4(sdst + q * 4, src + q, yv && (xx + q) < IMGS);
            }
        } else {
            const float* Ag = A + (size_t)m0 * K + kt * 32;
            #pragma unroll
            for (int i = 0; i < 2; i++) {
                int row = lrow + i * 32;
                uint32_t s = As_base + (buf * ASTG + swz(row, lc4)) * 4;
                cp16(s, Ag + (size_t)row * K + lc4, (m0 + row) < M);
            }
        }
        const float* Wg = W + (size_t)n0 * K + kt * 32;
        #pragma unroll
        for (int i = 0; i < 4; i++) {
            int row = lrow + i * 32;
            uint32_t s = Ws_base + (buf * 4096 + swz(row, lc4)) * 4;
            cp16(s, Wg + (size_t)row * K + lc4, true);
        }
    };

    load_tile(0, 0);
    cp_commit();
    if (ktiles > 1) { load_tile(1, 1); cp_commit(); }

    for (int kt = 0; kt < ktiles; kt++) {
        if (kt + 2 < ktiles) {
            load_tile(kt + 2, (kt + 2) % 3);
            cp_commit();
            cp_wait<2>();
        } else if (kt + 1 < ktiles) {
            cp_wait<1>();
        } else {
            cp_wait<0>();
        }
        __syncthreads();

        const uint32_t as_b = As_base + ((kt % 3) * ASTG) * 4;
        const uint32_t ws_b = Ws_base + ((kt % 3) * 4096) * 4;
        #pragma unroll
        for (int ks = 0; ks < 32; ks += 8) {
            uint32_t af[2][4];
            #pragma unroll
            for (int mt = 0; mt < 2; mt++) {
                int row = wm * 32 + mt * 16 + rowA_in;
                int col = ks + koffA;
                uint32_t addr = as_b + (uint32_t)swz(row, col) * 4;
                ldsm4(addr, af[mt][0], af[mt][1], af[mt][2], af[mt][3]);
            }
            #pragma unroll
            for (int np = 0; np < NP; np++) {
                int row = wn * WN + np * 16 + rowB_in;
                int col = ks + koffB;
                uint32_t addr = ws_b + (uint32_t)swz(row, col) * 4;
                uint32_t b0a, b1a, b0b, b1b;
                ldsm4(addr, b0a, b1a, b0b, b1b);
                mma_tf32(acc[0][2 * np    ], af[0], b0a, b1a);
                mma_tf32(acc[1][2 * np    ], af[1], b0a, b1a);
                mma_tf32(acc[0][2 * np + 1], af[0], b0b, b1b);
                mma_tf32(acc[1][2 * np + 1], af[1], b0b, b1b);
            }
        }
        __syncthreads();
    }

    // stats staging buffer (reuses As smem, free after mainloop)
    float* sp = smem;   // [4 wn][64 rows][2]

    #pragma unroll
    for (int mt = 0; mt < 2; mt++) {
        #pragma unroll
        for (int half = 0; half < 2; half++) {
            int rowl = wm * 32 + mt * 16 + half * 8 + gid;
            int m = m0 + rowl;
            bool mok = m < M;
            int mres = POSMOD ? (m % NTOK) : m;
            float la = 0.f, lc = 0.f;
            if (LNFUSE && mok) {
                float2 p0 = g_part[m];
                float2 p1 = g_part[MTOK + m];
                float s = p0.x + p1.x, q = p0.y + p1.y;
                float mean = s * (1.f / 256.f);
                float var  = q * (1.f / 256.f) - mean * mean;
                la = rsqrtf(var + 1e-5f);
                lc = -mean * la;
            }
            int ob = 0, opy = 0, opx = 0;
            if (RESHAPE && mok) {
                ob = m / NTOK;
                int n8 = m - ob * NTOK;
                opy = n8 / HP;
                opx = n8 - opy * HP;
            }
            float ss = 0.f, qq = 0.f;
            #pragma unroll
            for (int nt = 0; nt < NT; nt++) {
                int n = n0 + wn * WN + nt * 8 + tig * 2;
                float v0 = acc[mt][nt][half * 2 + 0];
                float v1 = acc[mt][nt][half * 2 + 1];
                if (LNFUSE) {
                    float2 S = *(const float2*)&Sarr[n];
                    float2 B = *(const float2*)&Barr[n];
                    v0 = fmaf(la, v0, fmaf(lc, S.x, B.x));
                    v1 = fmaf(la, v1, fmaf(lc, S.y, B.y));
                }
                if (HASBIAS) { v0 += bias[n]; v1 += bias[n + 1]; }
                if (ACT == 1) { v0 = gelu_exact(v0); v1 = gelu_exact(v1); }
                if (HASRES && mok) {
                    float2 r = *(const float2*)&res[(size_t)mres * Nn + n];
                    v0 += r.x; v1 += r.y;
                }
                if (TRUNC) { v0 = ftrunc_tf(v0); v1 = ftrunc_tf(v1); }
                if (STATS) {
                    ss += v0 + v1;
                    qq = fmaf(v0, v0, fmaf(v1, v1, qq));
                }
                if (mok) {
                    if (RESHAPE) {
                        int y  = opy * 16 + (n >> 4);
                        int xc = opx * 16 + (n & 15);
                        if (y < IMGS) {
                            float* orow = C + ((size_t)ob * IMGS + y) * IMGS;
                            if (xc < IMGS)     orow[xc]     = v0;
                            if (xc + 1 < IMGS) orow[xc + 1] = v1;
                        }
                    } else {
                        *(float2*)&C[(size_t)m * Nn + n] = make_float2(v0, v1);
                    }
                }
            }
            if (STATS) {
                ss += __shfl_xor_sync(0xffffffffu, ss, 1);
                ss += __shfl_xor_sync(0xffffffffu, ss, 2);
                qq += __shfl_xor_sync(0xffffffffu, qq, 1);
                qq += __shfl_xor_sync(0xffffffffu, qq, 2);
                if (tig == 0) {
                    sp[(wn * 64 + rowl) * 2 + 0] = ss;
                    sp[(wn * 64 + rowl) * 2 + 1] = qq;
                }
            }
        }
    }
    if (STATS) {
        __syncthreads();
        if (tid < 64) {
            int m = m0 + tid;
            if (m < M) {
                float s = 0.f, q = 0.f;
                #pragma unroll
                for (int w = 0; w < 4; w++) {
                    s += sp[(w * 64 + tid) * 2 + 0];
                    q += sp[(w * 64 + tid) * 2 + 1];
                }
                g_part[(size_t)blockIdx.x * MTOK + m] = make_float2(s, q);
            }
        }
    }
}

// ---------------- MMA flash attention, q-tile 128, 8 warps ----------------
__global__ void __launch_bounds__(256)
attn_mma(const float* __restrict__ scale_d) {
    __shared__ uint32_t Ks[32 * 36];
    __shared__ uint32_t Vs[32 * 40];
    __shared__ uint32_t Ps[8][16 * 36];

    const int bh = blockIdx.y;
    const int b = bh >> 3, h = bh & 7;
    const int tid = threadIdx.x;
    const int warp = tid >> 5, lane = tid & 31;
    const int gid = lane >> 2, tig = lane & 3;
    const int q0 = (gridDim.x - 1 - blockIdx.x) * 128;
    const float* base = g_qkv + (size_t)b * NTOK * 768;
    const float sc = scale_d[h];

    const int i0 = q0 + warp * 16 + gid;
    const int i1 = i0 + 8;

    uint32_t qf[4][4];
    #pragma unroll
    for (int ks = 0; ks < 4; ks++) {
        int c = h * 32 + ks * 8 + tig;
        float v00 = 0.f, v10 = 0.f, v01 = 0.f, v11 = 0.f;
        if (i0 < NTOK) { v00 = base[(size_t)i0 * 768 + c] * sc;
                         v01 = base[(size_t)i0 * 768 + c + 4] * sc; }
        if (i1 < NTOK) { v10 = base[(size_t)i1 * 768 + c] * sc;
                         v11 = base[(size_t)i1 * 768 + c + 4] * sc; }
        qf[ks][0] = f2tf(v00); qf[ks][1] = f2tf(v10);
        qf[ks][2] = f2tf(v01); qf[ks][3] = f2tf(v11);
    }

    float m0 = -1e30f, m1 = -1e30f, l0 = 0.f, l1 = 0.f;
    float oacc[4][4] = {};

    const int jmax = min(q0 + 127, NTOK - 1);
    for (int j0 = 0; j0 < jmax; j0 += 32) {
        __syncthreads();
        {
            int r  = tid >> 3;
            int c4 = (tid & 7) * 4;
            int j  = j0 + r;
            if (j < NTOK) {
                const float* kp = base + (size_t)j * 768 + 256 + h * 32 + c4;
                const float* vp = base + (size_t)j * 768 + 512 + h * 32 + c4;
                float4 ka = *(const float4*)kp;
                Ks[r * 36 + c4 + 0] = f2tf(ka.x); Ks[r * 36 + c4 + 1] = f2tf(ka.y);
                Ks[r * 36 + c4 + 2] = f2tf(ka.z); Ks[r * 36 + c4 + 3] = f2tf(ka.w);
                float4 va = *(const float4*)vp;
                Vs[r * 40 + c4 + 0] = f2tf(va.x); Vs[r * 40 + c4 + 1] = f2tf(va.y);
                Vs[r * 40 + c4 + 2] = f2tf(va.z); Vs[r * 40 + c4 + 3] = f2tf(va.w);
            } else {
                #pragma unroll
                for (int q = 0; q < 4; q++) {
                    Ks[r * 36 + c4 + q] = 0;
                    Vs[r * 40 + c4 + q] = 0;
                }
            }
        }
        __syncthreads();

        float s[4][4] = {};
        #pragma unroll
        for (int ks = 0; ks < 4; ks++) {
            #pragma unroll
            for (int nt = 0; nt < 4; nt++) {
                uint32_t b0 = Ks[(nt * 8 + gid) * 36 + ks * 8 + tig];
                uint32_t b1 = Ks[(nt * 8 + gid) * 36 + ks * 8 + tig + 4];
                mma_tf32(s[nt], qf[ks], b0, b1);
            }
        }

        float rm0 = -1e30f, rm1 = -1e30f;
        #pragma unroll
        for (int nt = 0; nt < 4; nt++) {
            int jc = j0 + nt * 8 + tig * 2;
            if (jc     >= i0) s[nt][0] = -1e30f;
            if (jc + 1 >= i0) s[nt][1] = -1e30f;
            if (jc     >= i1) s[nt][2] = -1e30f;
            if (jc + 1 >= i1) s[nt][3] = -1e30f;
            rm0 = fmaxf(rm0, fmaxf(s[nt][0], s[nt][1]));
            rm1 = fmaxf(rm1, fmaxf(s[nt][2], s[nt][3]));
        }
        rm0 = fmaxf(rm0, __shfl_xor_sync(0xffffffffu, rm0, 1));
        rm0 = fmaxf(rm0, __shfl_xor_sync(0xffffffffu, rm0, 2));
        rm1 = fmaxf(rm1, __shfl_xor_sync(0xffffffffu, rm1, 1));
        rm1 = fmaxf(rm1, __shfl_xor_sync(0xffffffffu, rm1, 2));
        float mn0 = fmaxf(m0, rm0), mn1 = fmaxf(m1, rm1);
        float corr0 = __expf(m0 - mn0), corr1 = __expf(m1 - mn1);

        float p[4][4];
        float ps0 = 0.f, ps1 = 0.f;
        #pragma unroll
        for (int nt = 0; nt < 4; nt++) {
            p[nt][0] = (s[nt][0] < -1e29f) ? 0.f : __expf(s[nt][0] - mn0);
            p[nt][1] = (s[nt][1] < -1e29f) ? 0.f : __expf(s[nt][1] - mn0);
            p[nt][2] = (s[nt][2] < -1e29f) ? 0.f : __expf(s[nt][2] - mn1);
            p[nt][3] = (s[nt][3] < -1e29f) ? 0.f : __expf(s[nt][3] - mn1);
            ps0 += p[nt][0] + p[nt][1];
            ps1 += p[nt][2] + p[nt][3];
        }
        ps0 += __shfl_xor_sync(0xffffffffu, ps0, 1);
        ps0 += __shfl_xor_sync(0xffffffffu, ps0, 2);
        ps1 += __shfl_xor_sync(0xffffffffu, ps1, 1);
        ps1 += __shfl_xor_sync(0xffffffffu, ps1, 2);
        l0 = l0 * corr0 + ps0;
        l1 = l1 * corr1 + ps1;
        #pragma unroll
        for (int nt = 0; nt < 4; nt++) {
            oacc[nt][0] *= corr0; oacc[nt][1] *= corr0;
            oacc[nt][2] *= corr1; oacc[nt][3] *= corr1;
        }

        uint32_t* pw = Ps[warp];
        __syncwarp();
        #pragma unroll
        for (int nt = 0; nt < 4; nt++) {
            pw[gid * 36 + nt * 8 + tig * 2    ]  = f2tf(p[nt][0]);
            pw[gid * 36 + nt * 8 + tig * 2 + 1]  = f2tf(p[nt][1]);
            pw[(gid + 8) * 36 + nt * 8 + tig * 2    ] = f2tf(p[nt][2]);
            pw[(gid + 8) * 36 + nt * 8 + tig * 2 + 1] = f2tf(p[nt][3]);
        }
        __syncwarp();

        #pragma unroll
        for (int ks = 0; ks < 4; ks++) {
            uint32_t af[4];
            af[0] = pw[gid * 36 + ks * 8 + tig];
            af[1] = pw[(gid + 8) * 36 + ks * 8 + tig];
            af[2] = pw[gid * 36 + ks * 8 + tig + 4];
            af[3] = pw[(gid + 8) * 36 + ks * 8 + tig + 4];
            #pragma unroll
            for (int nt = 0; nt < 4; nt++) {
                uint32_t b0 = Vs[(ks * 8 + tig) * 40 + nt * 8 + gid];
                uint32_t b1 = Vs[(ks * 8 + tig + 4) * 40 + nt * 8 + gid];
                mma_tf32(oacc[nt], af, b0, b1);
            }
        }
        m0 = mn0; m1 = mn1;
    }

    float inv0 = (l0 > 0.f) ? 1.f / l0 : 0.f;
    float inv1 = (l1 > 0.f) ? 1.f / l1 : 0.f;
    #pragma unroll
    for (int nt = 0; nt < 4; nt++) {
        int col = h * 32 + nt * 8 + tig * 2;
        if (i0 < NTOK) {
            float2 o = make_float2(ftrunc_tf(oacc[nt][0] * inv0),
                                   ftrunc_tf(oacc[nt][1] * inv0));
            *(float2*)&g_attn[((size_t)b * NTOK + i0) * DIM + col] = o;
        }
        if (i1 < NTOK) {
            float2 o = make_float2(ftrunc_tf(oacc[nt][2] * inv1),
                                   ftrunc_tf(oacc[nt][3] * inv1));
            *(float2*)&g_attn[((size_t)b * NTOK + i1) * DIM + col] = o;
        }
    }
}

// ---------------- host orchestration ---------------------------------------
static inline dim3 gg(int M, int Nn) { return dim3(Nn / 128, (M + 63) / 64); }

extern "C" void kernel_launch(void* const* d_in, const int* in_sizes, int n_in,
                              void* d_out, int out_size) {
    const float* x      = (const float*)d_in[0];
    const float* pos    = (const float*)d_in[1];
    const float* spt_w  = (const float*)d_in[2];
    const float* spt_b  = (const float*)d_in[3];
    const float* ln1_w  = (const float*)d_in[4];
    const float* ln1_b  = (const float*)d_in[5];
    const float* scale  = (const float*)d_in[6];
    const float* wqkv   = (const float*)d_in[7];
    const float* wout   = (const float*)d_in[8];
    const float* bout   = (const float*)d_in[9];
    const float* ln2_w  = (const float*)d_in[10];
    const float* ln2_b  = (const float*)d_in[11];
    const float* ff1_w  = (const float*)d_in[12];
    const float* ff1_b  = (const float*)d_in[13];
    const float* ff2_w  = (const float*)d_in[14];
    const float* ff2_b  = (const float*)d_in[15];
    const float* pix_w  = (const float*)d_in[16];
    const float* pix_b  = (const float*)d_in[17];

    float *t, *qkv, *attn, *ff, *wtf, *lnS, *lnB;
    cudaGetSymbolAddress((void**)&t,    g_t);
    cudaGetSymbolAddress((void**)&qkv,  g_qkv);
    cudaGetSymbolAddress((void**)&attn, g_attn);
    cudaGetSymbolAddress((void**)&ff,   g_ff);
    cudaGetSymbolAddress((void**)&wtf,  g_wtf);
    cudaGetSymbolAddress((void**)&lnS,  g_lnS);
    cudaGetSymbolAddress((void**)&lnB,  g_lnB);

    // variants:
    // spt:  GATHER + POSMOD res + TRUNC + STATS
    // qkv:  LNFUSE
    // wout: res + TRUNC + STATS
    // ff1:  LNFUSE + bias + GELU + TRUNC
    // ff2:  res + TRUNC + STATS
    // pix:  RESHAPE
    cudaFuncSetAttribute(gemm_tc<2, 0, true,  true,  true,  true,  true,  false, false, true >, cudaFuncAttributeMaxDynamicSharedMemorySize, GEMM_SMEM);
    cudaFuncSetAttribute(gemm_tc<3, 0, false, false, false, false, false, false, true,  false>, cudaFuncAttributeMaxDynamicSharedMemorySize, GEMM_SMEM);
    cudaFuncSetAttribute(gemm_tc<3, 0, true,  true,  false, true,  false, false, false, true >, cudaFuncAttributeMaxDynamicSharedMemorySize, GEMM_SMEM);
    cudaFuncSetAttribute(gemm_tc<3, 1, true,  false, false, true,  false, false, true,  false>, cudaFuncAttributeMaxDynamicSharedMemorySize, GEMM_SMEM);
    cudaFuncSetAttribute(gemm_tc<2, 0, true,  false, false, false, false, true,  false, false>, cudaFuncAttributeMaxDynamicSharedMemorySize, GEMM_SMEM);

    convert_w<<<(W_TOTAL / 4 + 255) / 256, 256>>>(spt_w, wqkv, wout, ff1_w, ff2_w, pix_w,
                                                  ln1_w, ln2_w);
    colsum_kernel<<<(3 * LNC_PER + 7) / 8, 256>>>(wqkv, ff1_w, ln1_b, ln2_b);

    // spt projection: fused tokenize gather + pos residual + row stats
    gemm_tc<2, 0, true, true, true, true, true, false, false, true><<<gg(MTOK, DIM), 256, GEMM_SMEM>>>(
        x, wtf + W_SPT_OFF, spt_b, pos, t, nullptr, nullptr, MTOK, DIM, 1280);

    for (int d = 0; d < 3; d++) {
        // qkv GEMM with epilogue LN (stats from producer partials)
        gemm_tc<3, 0, false, false, false, false, false, false, true, false><<<gg(MTOK, 768), 256, GEMM_SMEM>>>(
            t, wtf + W_QKV_OFF + (size_t)d * 768 * DIM, nullptr, nullptr, qkv,
            lnS + d * LNC_PER, lnB + d * LNC_PER, MTOK, 768, DIM);
        {
            dim3 grid((NTOK + 127) / 128, BATCH * NHEADS);
            attn_mma<<<grid, 256>>>(scale + d * NHEADS);
        }
        // wout: residual into t + row stats (for LN2)
        gemm_tc<3, 0, true, true, false, true, false, false, false, true><<<gg(MTOK, DIM), 256, GEMM_SMEM>>>(
            attn, wtf + W_WOUT_OFF + (size_t)d * DIM * DIM, bout + d * DIM, t, t,
            nullptr, nullptr, MTOK, DIM, DIM);
        // ff1 GEMM with epilogue LN + bias + GELU
        gemm_tc<3, 1, true, false, false, true, false, false, true, false><<<gg(MTOK, 1024), 256, GEMM_SMEM>>>(
            t, wtf + W_FF1_OFF + (size_t)d * 1024 * DIM, ff1_b + d * 1024, nullptr, ff,
            lnS + d * LNC_PER + 768, lnB + d * LNC_PER + 768, MTOK, 1024, DIM);
        // ff2: residual into t + row stats (for next layer LN1)
        gemm_tc<3, 0, true, true, false, true, false, false, false, true><<<gg(MTOK, DIM), 256, GEMM_SMEM>>>(
            ff, wtf + W_FF2_OFF + (size_t)d * DIM * 1024, ff2_b + d * DIM, t, t,
            nullptr, nullptr, MTOK, DIM, 1024);
    }

    // pix projection with fused untokenize + crop (writes d_out directly)
    gemm_tc<2, 0, true, false, false, false, false, true, false, false><<<gg(MTOK, DIM), 256, GEMM_SMEM>>>(
        t, wtf + W_PIX_OFF, pix_b, nullptr, (float*)d_out, nullptr, nullptr, MTOK, DIM, DIM);
}

// round 17
// speedup vs baseline: 1.0629x; 1.0123x over previous
#include <cuda_runtime.h>
#include <math.h>
#include <stdint.h>

#define IMGS   457
#define HPAD   464
#define HP     29
#define NTOK   841
#define BATCH  8
#define DIM    256
#define MTOK   (BATCH*NTOK)   // 6728
#define NHEADS 8
#define DH     32

// ---------------- scratch (device globals; no allocations) ----------------
__device__ float g_t   [MTOK*DIM];
__device__ float g_qkv [MTOK*768];
__device__ float g_attn[MTOK*DIM];
__device__ float g_ff  [MTOK*1024];
__device__ float2 g_part[2*MTOK];   // per-CTA-x partial (sum, sumsq) of t rows

// pre-truncated (tf32) weights, with LN gamma folded into qkv/ff1
#define W_SPT_OFF  0
#define W_SPT_SZ   (256*1280)
#define W_QKV_OFF  (W_SPT_OFF+W_SPT_SZ)
#define W_QKV_SZ   (3*768*256)
#define W_WOUT_OFF (W_QKV_OFF+W_QKV_SZ)
#define W_WOUT_SZ  (3*256*256)
#define W_FF1_OFF  (W_WOUT_OFF+W_WOUT_SZ)
#define W_FF1_SZ   (3*1024*256)
#define W_FF2_OFF  (W_FF1_OFF+W_FF1_SZ)
#define W_FF2_SZ   (3*256*1024)
#define W_PIX_OFF  (W_FF2_OFF+W_FF2_SZ)
#define W_PIX_SZ   (256*256)
#define W_TOTAL    (W_PIX_OFF+W_PIX_SZ)
__device__ float g_wtf[W_TOTAL];

// per-layer LN column terms: [layer][ qkv 768 | ff1 1024 ]
#define LNC_PER 1792
__device__ float g_lnS[3*LNC_PER];
__device__ float g_lnB[3*LNC_PER];

__device__ __forceinline__ uint32_t f2tf(float f) {
    uint32_t r;
    asm("cvt.rna.tf32.f32 %0, %1;" : "=r"(r) : "f"(f));
    return r;
}
__device__ __forceinline__ float ftrunc_tf(float f) { return __uint_as_float(f2tf(f)); }

// ---------- weight conversion: tf32 truncate + fold LN gamma --------------
__global__ void convert_w(const float* __restrict__ spt, const float* __restrict__ qkv,
                          const float* __restrict__ wo, const float* __restrict__ f1,
                          const float* __restrict__ f2w, const float* __restrict__ px,
                          const float* __restrict__ ln1w, const float* __restrict__ ln2w) {
    int i4 = blockIdx.x * 256 + threadIdx.x;
    if (i4 >= W_TOTAL / 4) return;
    int i = i4 * 4;
    const float* src; int off;
    if      (i < W_QKV_OFF)  { src = spt; off = 0; }
    else if (i < W_WOUT_OFF) { src = qkv; off = W_QKV_OFF; }
    else if (i < W_FF1_OFF)  { src = wo;  off = W_WOUT_OFF; }
    else if (i < W_FF2_OFF)  { src = f1;  off = W_FF1_OFF; }
    else if (i < W_PIX_OFF)  { src = f2w; off = W_FF2_OFF; }
    else                     { src = px;  off = W_PIX_OFF; }
    float4 v = *(const float4*)(src + (i - off));
    if (i >= W_QKV_OFF && i < W_WOUT_OFF) {
        int rel = i - W_QKV_OFF;
        int d = rel / (768 * 256);
        int k = rel & 255;
        float4 g = *(const float4*)(ln1w + d * 256 + k);
        v.x *= g.x; v.y *= g.y; v.z *= g.z; v.w *= g.w;
    } else if (i >= W_FF1_OFF && i < W_FF2_OFF) {
        int rel = i - W_FF1_OFF;
        int d = rel / (1024 * 256);
        int k = rel & 255;
        float4 g = *(const float4*)(ln2w + d * 256 + k);
        v.x *= g.x; v.y *= g.y; v.z *= g.z; v.w *= g.w;
    }
    v.x = ftrunc_tf(v.x); v.y = ftrunc_tf(v.y);
    v.z = ftrunc_tf(v.z); v.w = ftrunc_tf(v.w);
    *(float4*)&g_wtf[i] = v;
}

// ---------- colsum: S[n] = sum_k W'[n,k];  B2[n] = sum_k W[n,k]*beta[k] ---
__global__ void colsum_kernel(const float* __restrict__ wqkv, const float* __restrict__ f1w,
                              const float* __restrict__ ln1b, const float* __restrict__ ln2b) {
    int n = blockIdx.x * 8 + (threadIdx.x >> 5);
    if (n >= 3 * LNC_PER) return;
    int d = n / LNC_PER, r = n % LNC_PER;
    const float* wt; const float* worig; const float* bln;
    if (r < 768) {
        wt = g_wtf + W_QKV_OFF + (size_t)d * 768 * 256 + (size_t)r * 256;
        worig = wqkv + (size_t)d * 768 * 256 + (size_t)r * 256;
        bln = ln1b + d * 256;
    } else {
        int rr = r - 768;
        wt = g_wtf + W_FF1_OFF + (size_t)d * 1024 * 256 + (size_t)rr * 256;
        worig = f1w + (size_t)d * 1024 * 256 + (size_t)rr * 256;
        bln = ln2b + d * 256;
    }
    int lane = threadIdx.x & 31;
    float s = 0.f, b = 0.f;
    #pragma unroll
    for (int k = lane; k < 256; k += 32) { s += wt[k]; b += worig[k] * bln[k]; }
    #pragma unroll
    for (int o = 16; o; o >>= 1) {
        s += __shfl_xor_sync(0xffffffffu, s, o);
        b += __shfl_xor_sync(0xffffffffu, b, o);
    }
    if (lane == 0) { g_lnS[n] = s; g_lnB[n] = b; }
}

// ---------------- tf32 tensor-core GEMM, BM=64, 3-stage cp.async, LDSM ----
__device__ __forceinline__ void mma_tf32(float c[4], const uint32_t a[4],
                                         uint32_t b0, uint32_t b1) {
    asm volatile(
        "mma.sync.aligned.m16n8k8.row.col.f32.tf32.tf32.f32 "
        "{%0,%1,%2,%3}, {%4,%5,%6,%7}, {%8,%9}, {%0,%1,%2,%3};"
        : "+f"(c[0]), "+f"(c[1]), "+f"(c[2]), "+f"(c[3])
        : "r"(a[0]), "r"(a[1]), "r"(a[2]), "r"(a[3]), "r"(b0), "r"(b1));
}
__device__ __forceinline__ float gelu_exact(float v) {
    return 0.5f * v * (1.0f + erff(v * 0.70710678118654752440f));
}
__device__ __forceinline__ void cp16(uint32_t saddr, const float* g, bool pred) {
    asm volatile("cp.async.cg.shared.global [%0], [%1], 16, %2;"
                 :: "r"(saddr), "l"(g), "r"(pred ? 16 : 0));
}
__device__ __forceinline__ void cp4(uint32_t saddr, const float* g, bool pred) {
    asm volatile("cp.async.ca.shared.global [%0], [%1], 4, %2;"
                 :: "r"(saddr), "l"(g), "r"(pred ? 4 : 0));
}
__device__ __forceinline__ void cp_commit() { asm volatile("cp.async.commit_group;"); }
template<int N>
__device__ __forceinline__ void cp_wait() {
    asm volatile("cp.async.wait_group %0;" :: "n"(N));
}
__device__ __forceinline__ int swz(int row, int col) {
    return row * 32 + (col ^ ((row & 7) * 4));
}
__device__ __forceinline__ void ldsm4(uint32_t addr, uint32_t& r0, uint32_t& r1,
                                      uint32_t& r2, uint32_t& r3) {
    asm volatile("ldmatrix.sync.aligned.m8n8.x4.shared.b16 {%0,%1,%2,%3}, [%4];"
                 : "=r"(r0), "=r"(r1), "=r"(r2), "=r"(r3) : "r"(addr));
}

#define GEMM_SMEM (3 * (64 * 32 + 4096) * 4)   // 73728 B

template<int MINB, int ACT, bool HASBIAS, bool HASRES, bool POSMOD, bool TRUNC,
         bool GATHER, bool RESHAPE, bool LNFUSE, bool STATS>
__global__ void __launch_bounds__(256, MINB)
gemm_tc(const float* __restrict__ A, const float* __restrict__ W,
        const float* __restrict__ bias, const float* __restrict__ res,
        float* __restrict__ C, const float* __restrict__ Sarr,
        const float* __restrict__ Barr, int M, int Nn, int K) {
    constexpr int BM = 64;
    constexpr int NWM = 2;
    constexpr int WN  = 32;
    constexpr int NP  = 2;
    constexpr int NT  = 4;
    constexpr int ASTG = BM * 32;

    extern __shared__ float smem[];
    float* As = smem;
    float* Ws = smem + 3 * ASTG;
    const int tid  = threadIdx.x;
    const int wid  = tid >> 5, lane = tid & 31;
    const int wm   = wid % NWM, wn = wid / NWM;
    const int gid  = lane >> 2, tig = lane & 3;
    const int m0   = blockIdx.y * BM, n0 = blockIdx.x * 128;

    const int lrow = tid >> 3;
    const int lc4  = (tid & 7) * 4;

    uint32_t As_base = (uint32_t)__cvta_generic_to_shared(As);
    uint32_t Ws_base = (uint32_t)__cvta_generic_to_shared(Ws);

    const int rowA_in  = (lane & 15);
    const int koffA    = ((lane >> 4) & 1) * 4;
    const int rowB_in  = (lane & 7) + (((lane >> 4) & 1) << 3);
    const int koffB    = ((lane >> 3) & 1) * 4;

    bool grow[2];
    int  gb[2], gpy[2], gpx[2];
    if (GATHER) {
        #pragma unroll
        for (int i = 0; i < 2; i++) {
            int m = m0 + lrow + i * 32;
            grow[i] = m < M;
            int mm = m < M ? m : (M - 1);
            gb[i] = mm / NTOK;
            int n8 = mm - gb[i] * NTOK;
            gpy[i] = n8 / HP;
            gpx[i] = n8 - gpy[i] * HP;
        }
    }

    float acc[2][NT][4] = {};
    const int ktiles = K >> 5;

    auto load_tile = [&](int kt, int buf) {
        if (GATHER) {
            int c  = kt * 32 + lc4;
            int s  = c >> 8;
            int pr = (c >> 4) & 15;
            int pc = c & 15;
            int dy = (s == 0) ? 0 : ((s <= 2) ? -8 : 8);
            int dx = (s == 0) ? 0 : ((s & 1) ? -8 : 8);
            #pragma unroll
            for (int i = 0; i < 2; i++) {
                int row = lrow + i * 32;
                uint32_t sdst = As_base + (buf * ASTG + swz(row, lc4)) * 4;
                int y  = gpy[i] * 16 + pr - dy;
                if (y < 0) y += HPAD; if (y >= HPAD) y -= HPAD;
                int xx = gpx[i] * 16 + pc - dx;
                if (xx < 0) xx += HPAD; if (xx >= HPAD) xx -= HPAD;
                bool yv = grow[i] && (y < IMGS);
                const float* src = A + ((size_t)gb[i] * IMGS + y) * IMGS + xx;
                #pragma unroll
                for (int q = 0; q < 4; q++)
                    cp4(sdst + q * 4, src + q, yv && (xx + q) < IMGS);
            }
        } else {
            const float* Ag = A + (size_t)m0 * K + kt * 32;
            #pragma unroll
            for (int i = 0; i < 2; i++) {
                int row = lrow + i * 32;
                uint32_t s = As_base + (buf * ASTG + swz(row, lc4)) * 4;
                cp16(s, Ag + (size_t)row * K + lc4, (m0 + row) < M);
            }
        }
        const float* Wg = W + (size_t)n0 * K + kt * 32;
        #pragma unroll
        for (int i = 0; i < 4; i++) {
            int row = lrow + i * 32;
            uint32_t s = Ws_base + (buf * 4096 + swz(row, lc4)) * 4;
            cp16(s, Wg + (size_t)row * K + lc4, true);
        }
    };

    load_tile(0, 0);
    cp_commit();
    if (ktiles > 1) { load_tile(1, 1); cp_commit(); }

    for (int kt = 0; kt < ktiles; kt++) {
        if (kt + 2 < ktiles) {
            load_tile(kt + 2, (kt + 2) % 3);
            cp_commit();
            cp_wait<2>();
        } else if (kt + 1 < ktiles) {
            cp_wait<1>();
        } else {
            cp_wait<0>();
        }
        __syncthreads();

        const uint32_t as_b = As_base + ((kt % 3) * ASTG) * 4;
        const uint32_t ws_b = Ws_base + ((kt % 3) * 4096) * 4;
        #pragma unroll
        for (int ks = 0; ks < 32; ks += 8) {
            uint32_t af[2][4];
            #pragma unroll
            for (int mt = 0; mt < 2; mt++) {
                int row = wm * 32 + mt * 16 + rowA_in;
                int col = ks + koffA;
                uint32_t addr = as_b + (uint32_t)swz(row, col) * 4;
                ldsm4(addr, af[mt][0], af[mt][1], af[mt][2], af[mt][3]);
            }
            #pragma unroll
            for (int np = 0; np < NP; np++) {
                int row = wn * WN + np * 16 + rowB_in;
                int col = ks + koffB;
                uint32_t addr = ws_b + (uint32_t)swz(row, col) * 4;
                uint32_t b0a, b1a, b0b, b1b;
                ldsm4(addr, b0a, b1a, b0b, b1b);
                mma_tf32(acc[0][2 * np    ], af[0], b0a, b1a);
                mma_tf32(acc[1][2 * np    ], af[1], b0a, b1a);
                mma_tf32(acc[0][2 * np + 1], af[0], b0b, b1b);
                mma_tf32(acc[1][2 * np + 1], af[1], b0b, b1b);
            }
        }
        __syncthreads();
    }

    float* sp = smem;   // stats staging (reuses As smem)

    #pragma unroll
    for (int mt = 0; mt < 2; mt++) {
        #pragma unroll
        for (int half = 0; half < 2; half++) {
            int rowl = wm * 32 + mt * 16 + half * 8 + gid;
            int m = m0 + rowl;
            bool mok = m < M;
            int mres = POSMOD ? (m % NTOK) : m;
            float la = 0.f, lc = 0.f;
            if (LNFUSE && mok) {
                float2 p0 = g_part[m];
                float2 p1 = g_part[MTOK + m];
                float s = p0.x + p1.x, q = p0.y + p1.y;
                float mean = s * (1.f / 256.f);
                float var  = q * (1.f / 256.f) - mean * mean;
                la = rsqrtf(var + 1e-5f);
                lc = -mean * la;
            }
            int ob = 0, opy = 0, opx = 0;
            if (RESHAPE && mok) {
                ob = m / NTOK;
                int n8 = m - ob * NTOK;
                opy = n8 / HP;
                opx = n8 - opy * HP;
            }
            float ss = 0.f, qq = 0.f;
            #pragma unroll
            for (int nt = 0; nt < NT; nt++) {
                int n = n0 + wn * WN + nt * 8 + tig * 2;
                float v0 = acc[mt][nt][half * 2 + 0];
                float v1 = acc[mt][nt][half * 2 + 1];
                if (LNFUSE) {
                    float2 S = *(const float2*)&Sarr[n];
                    float2 B = *(const float2*)&Barr[n];
                    v0 = fmaf(la, v0, fmaf(lc, S.x, B.x));
                    v1 = fmaf(la, v1, fmaf(lc, S.y, B.y));
                }
                if (HASBIAS) { v0 += bias[n]; v1 += bias[n + 1]; }
                if (ACT == 1) { v0 = gelu_exact(v0); v1 = gelu_exact(v1); }
                if (HASRES && mok) {
                    float2 r = *(const float2*)&res[(size_t)mres * Nn + n];
                    v0 += r.x; v1 += r.y;
                }
                if (TRUNC) { v0 = ftrunc_tf(v0); v1 = ftrunc_tf(v1); }
                if (STATS) {
                    ss += v0 + v1;
                    qq = fmaf(v0, v0, fmaf(v1, v1, qq));
                }
                if (mok) {
                    if (RESHAPE) {
                        int y  = opy * 16 + (n >> 4);
                        int xc = opx * 16 + (n & 15);
                        if (y < IMGS) {
                            float* orow = C + ((size_t)ob * IMGS + y) * IMGS;
                            if (xc < IMGS)     orow[xc]     = v0;
                            if (xc + 1 < IMGS) orow[xc + 1] = v1;
                        }
                    } else {
                        *(float2*)&C[(size_t)m * Nn + n] = make_float2(v0, v1);
                    }
                }
            }
            if (STATS) {
                ss += __shfl_xor_sync(0xffffffffu, ss, 1);
                ss += __shfl_xor_sync(0xffffffffu, ss, 2);
                qq += __shfl_xor_sync(0xffffffffu, qq, 1);
                qq += __shfl_xor_sync(0xffffffffu, qq, 2);
                if (tig == 0) {
                    sp[(wn * 64 + rowl) * 2 + 0] = ss;
                    sp[(wn * 64 + rowl) * 2 + 1] = qq;
                }
            }
        }
    }
    if (STATS) {
        __syncthreads();
        if (tid < 64) {
            int m = m0 + tid;
            if (m < M) {
                float s = 0.f, q = 0.f;
                #pragma unroll
                for (int w = 0; w < 4; w++) {
                    s += sp[(w * 64 + tid) * 2 + 0];
                    q += sp[(w * 64 + tid) * 2 + 1];
                }
                g_part[(size_t)blockIdx.x * MTOK + m] = make_float2(s, q);
            }
        }
    }
}

// ---------------- MMA flash attention, q-tile 128, j-tile 64, cp.async ----
// dyn smem: Ks[2][64*36] Vs[2][64*40] Ps[8][16*36] = 57344 B
#define ATT_SMEM ((2*64*36 + 2*64*40 + 8*16*36) * 4)

__global__ void __launch_bounds__(256)
attn_mma(const float* __restrict__ scale_d) {
    extern __shared__ uint32_t asm_[];
    uint32_t* Ks = asm_;                    // [2][64*36]
    uint32_t* Vs = asm_ + 2 * 64 * 36;      // [2][64*40]
    uint32_t* Ps = asm_ + 2 * 64 * 36 + 2 * 64 * 40;  // [8][16*36]

    const int bh = blockIdx.y;
    const int b = bh >> 3, h = bh & 7;
    const int tid = threadIdx.x;
    const int warp = tid >> 5, lane = tid & 31;
    const int gid = lane >> 2, tig = lane & 3;
    const int q0 = (gridDim.x - 1 - blockIdx.x) * 128;
    const float* base = g_qkv + (size_t)b * NTOK * 768;
    const float sc = scale_d[h];

    const int i0 = q0 + warp * 16 + gid;
    const int i1 = i0 + 8;

    uint32_t Ks_s = (uint32_t)__cvta_generic_to_shared(Ks);
    uint32_t Vs_s = (uint32_t)__cvta_generic_to_shared(Vs);

    uint32_t qf[4][4];
    #pragma unroll
    for (int ks = 0; ks < 4; ks++) {
        int c = h * 32 + ks * 8 + tig;
        float v00 = 0.f, v10 = 0.f, v01 = 0.f, v11 = 0.f;
        if (i0 < NTOK) { v00 = base[(size_t)i0 * 768 + c] * sc;
                         v01 = base[(size_t)i0 * 768 + c + 4] * sc; }
        if (i1 < NTOK) { v10 = base[(size_t)i1 * 768 + c] * sc;
                         v11 = base[(size_t)i1 * 768 + c + 4] * sc; }
        qf[ks][0] = f2tf(v00); qf[ks][1] = f2tf(v10);
        qf[ks][2] = f2tf(v01); qf[ks][3] = f2tf(v11);
    }

    float m0 = -1e30f, m1 = -1e30f, l0 = 0.f, l1 = 0.f;
    float oacc[4][4] = {};

    const int jmax = min(q0 + 127, NTOK - 1);
    const int ntile = (jmax + 63) >> 6;

    // tile loader: 64 rows, each thread loads 8 K + 8 V floats via cp.async
    const int lr  = tid >> 2;          // 0..63
    const int lc8 = (tid & 3) * 8;     // 0,8,16,24
    auto load_kv = [&](int t, int buf) {
        int j = t * 64 + lr;
        bool p = j < NTOK;
        const float* kp = base + (size_t)j * 768 + 256 + h * 32 + lc8;
        const float* vp = base + (size_t)j * 768 + 512 + h * 32 + lc8;
        uint32_t kd = Ks_s + (buf * 64 * 36 + lr * 36 + lc8) * 4;
        uint32_t vd = Vs_s + (buf * 64 * 40 + lr * 40 + lc8) * 4;
        cp16(kd,      kp,     p);
        cp16(kd + 16, kp + 4, p);
        cp16(vd,      vp,     p);
        cp16(vd + 16, vp + 4, p);
    };

    load_kv(0, 0);
    cp_commit();

    for (int t = 0; t < ntile; t++) {
        int buf = t & 1;
        if (t + 1 < ntile) { load_kv(t + 1, buf ^ 1); cp_commit(); cp_wait<1>(); }
        else               { cp_wait<0>(); }
        __syncthreads();

        const uint32_t* kb = Ks + buf * 64 * 36;
        const uint32_t* vb = Vs + buf * 64 * 40;

        #pragma unroll
        for (int sub = 0; sub < 2; sub++) {
            int jb = t * 64 + sub * 32;
            if (jb >= jmax) break;
            const uint32_t* kt_ = kb + sub * 32 * 36;
            const uint32_t* vt_ = vb + sub * 32 * 40;

            float s[4][4] = {};
            #pragma unroll
            for (int ks = 0; ks < 4; ks++) {
                #pragma unroll
                for (int nt = 0; nt < 4; nt++) {
                    uint32_t b0 = kt_[(nt * 8 + gid) * 36 + ks * 8 + tig];
                    uint32_t b1 = kt_[(nt * 8 + gid) * 36 + ks * 8 + tig + 4];
                    mma_tf32(s[nt], qf[ks], b0, b1);
                }
            }

            float rm0 = -1e30f, rm1 = -1e30f;
            #pragma unroll
            for (int nt = 0; nt < 4; nt++) {
                int jc = jb + nt * 8 + tig * 2;
                if (jc     >= i0) s[nt][0] = -1e30f;
                if (jc + 1 >= i0) s[nt][1] = -1e30f;
                if (jc     >= i1) s[nt][2] = -1e30f;
                if (jc + 1 >= i1) s[nt][3] = -1e30f;
                rm0 = fmaxf(rm0, fmaxf(s[nt][0], s[nt][1]));
                rm1 = fmaxf(rm1, fmaxf(s[nt][2], s[nt][3]));
            }
            rm0 = fmaxf(rm0, __shfl_xor_sync(0xffffffffu, rm0, 1));
            rm0 = fmaxf(rm0, __shfl_xor_sync(0xffffffffu, rm0, 2));
            rm1 = fmaxf(rm1, __shfl_xor_sync(0xffffffffu, rm1, 1));
            rm1 = fmaxf(rm1, __shfl_xor_sync(0xffffffffu, rm1, 2));
            float mn0 = fmaxf(m0, rm0), mn1 = fmaxf(m1, rm1);
            float corr0 = __expf(m0 - mn0), corr1 = __expf(m1 - mn1);

            float p[4][4];
            float ps0 = 0.f, ps1 = 0.f;
            #pragma unroll
            for (int nt = 0; nt < 4; nt++) {
                p[nt][0] = (s[nt][0] < -1e29f) ? 0.f : __expf(s[nt][0] - mn0);
                p[nt][1] = (s[nt][1] < -1e29f) ? 0.f : __expf(s[nt][1] - mn0);
                p[nt][2] = (s[nt][2] < -1e29f) ? 0.f : __expf(s[nt][2] - mn1);
                p[nt][3] = (s[nt][3] < -1e29f) ? 0.f : __expf(s[nt][3] - mn1);
                ps0 += p[nt][0] + p[nt][1];
                ps1 += p[nt][2] + p[nt][3];
            }
            ps0 += __shfl_xor_sync(0xffffffffu, ps0, 1);
            ps0 += __shfl_xor_sync(0xffffffffu, ps0, 2);
            ps1 += __shfl_xor_sync(0xffffffffu, ps1, 1);
            ps1 += __shfl_xor_sync(0xffffffffu, ps1, 2);
            l0 = l0 * corr0 + ps0;
            l1 = l1 * corr1 + ps1;
            #pragma unroll
            for (int nt = 0; nt < 4; nt++) {
                oacc[nt][0] *= corr0; oacc[nt][1] *= corr0;
                oacc[nt][2] *= corr1; oacc[nt][3] *= corr1;
            }

            uint32_t* pw = Ps + warp * 16 * 36;
            __syncwarp();
            #pragma unroll
            for (int nt = 0; nt < 4; nt++) {
                pw[gid * 36 + nt * 8 + tig * 2    ]  = f2tf(p[nt][0]);
                pw[gid * 36 + nt * 8 + tig * 2 + 1]  = f2tf(p[nt][1]);
                pw[(gid + 8) * 36 + nt * 8 + tig * 2    ] = f2tf(p[nt][2]);
                pw[(gid + 8) * 36 + nt * 8 + tig * 2 + 1] = f2tf(p[nt][3]);
            }
            __syncwarp();

            #pragma unroll
            for (int ks = 0; ks < 4; ks++) {
                uint32_t af[4];
                af[0] = pw[gid * 36 + ks * 8 + tig];
                af[1] = pw[(gid + 8) * 36 + ks * 8 + tig];
                af[2] = pw[gid * 36 + ks * 8 + tig + 4];
                af[3] = pw[(gid + 8) * 36 + ks * 8 + tig + 4];
                #pragma unroll
                for (int nt = 0; nt < 4; nt++) {
                    uint32_t b0 = vt_[(ks * 8 + tig) * 40 + nt * 8 + gid];
                    uint32_t b1 = vt_[(ks * 8 + tig + 4) * 40 + nt * 8 + gid];
                    mma_tf32(oacc[nt], af, b0, b1);
                }
            }
            m0 = mn0; m1 = mn1;
        }
        __syncthreads();
    }

    float inv0 = (l0 > 0.f) ? 1.f / l0 : 0.f;
    float inv1 = (l1 > 0.f) ? 1.f / l1 : 0.f;
    #pragma unroll
    for (int nt = 0; nt < 4; nt++) {
        int col = h * 32 + nt * 8 + tig * 2;
        if (i0 < NTOK) {
            float2 o = make_float2(ftrunc_tf(oacc[nt][0] * inv0),
                                   ftrunc_tf(oacc[nt][1] * inv0));
            *(float2*)&g_attn[((size_t)b * NTOK + i0) * DIM + col] = o;
        }
        if (i1 < NTOK) {
            float2 o = make_float2(ftrunc_tf(oacc[nt][2] * inv1),
                                   ftrunc_tf(oacc[nt][3] * inv1));
            *(float2*)&g_attn[((size_t)b * NTOK + i1) * DIM + col] = o;
        }
    }
}

// ---------------- host orchestration ---------------------------------------
static inline dim3 gg(int M, int Nn) { return dim3(Nn / 128, (M + 63) / 64); }

extern "C" void kernel_launch(void* const* d_in, const int* in_sizes, int n_in,
                              void* d_out, int out_size) {
    const float* x      = (const float*)d_in[0];
    const float* pos    = (const float*)d_in[1];
    const float* spt_w  = (const float*)d_in[2];
    const float* spt_b  = (const float*)d_in[3];
    const float* ln1_w  = (const float*)d_in[4];
    const float* ln1_b  = (const float*)d_in[5];
    const float* scale  = (const float*)d_in[6];
    const float* wqkv   = (const float*)d_in[7];
    const float* wout   = (const float*)d_in[8];
    const float* bout   = (const float*)d_in[9];
    const float* ln2_w  = (const float*)d_in[10];
    const float* ln2_b  = (const float*)d_in[11];
    const float* ff1_w  = (const float*)d_in[12];
    const float* ff1_b  = (const float*)d_in[13];
    const float* ff2_w  = (const float*)d_in[14];
    const float* ff2_b  = (const float*)d_in[15];
    const float* pix_w  = (const float*)d_in[16];
    const float* pix_b  = (const float*)d_in[17];

    float *t, *qkv, *attn, *ff, *wtf, *lnS, *lnB;
    cudaGetSymbolAddress((void**)&t,    g_t);
    cudaGetSymbolAddress((void**)&qkv,  g_qkv);
    cudaGetSymbolAddress((void**)&attn, g_attn);
    cudaGetSymbolAddress((void**)&ff,   g_ff);
    cudaGetSymbolAddress((void**)&wtf,  g_wtf);
    cudaGetSymbolAddress((void**)&lnS,  g_lnS);
    cudaGetSymbolAddress((void**)&lnB,  g_lnB);

    cudaFuncSetAttribute(gemm_tc<2, 0, true,  true,  true,  true,  true,  false, false, true >, cudaFuncAttributeMaxDynamicSharedMemorySize, GEMM_SMEM);
    cudaFuncSetAttribute(gemm_tc<3, 0, false, false, false, false, false, false, true,  false>, cudaFuncAttributeMaxDynamicSharedMemorySize, GEMM_SMEM);
    cudaFuncSetAttribute(gemm_tc<3, 0, true,  true,  false, true,  false, false, false, true >, cudaFuncAttributeMaxDynamicSharedMemorySize, GEMM_SMEM);
    cudaFuncSetAttribute(gemm_tc<3, 1, true,  false, false, true,  false, false, true,  false>, cudaFuncAttributeMaxDynamicSharedMemorySize, GEMM_SMEM);
    cudaFuncSetAttribute(gemm_tc<2, 0, true,  false, false, false, false, true,  false, false>, cudaFuncAttributeMaxDynamicSharedMemorySize, GEMM_SMEM);
    cudaFuncSetAttribute(attn_mma, cudaFuncAttributeMaxDynamicSharedMemorySize, ATT_SMEM);

    convert_w<<<(W_TOTAL / 4 + 255) / 256, 256>>>(spt_w, wqkv, wout, ff1_w, ff2_w, pix_w,
                                                  ln1_w, ln2_w);
    colsum_kernel<<<(3 * LNC_PER + 7) / 8, 256>>>(wqkv, ff1_w, ln1_b, ln2_b);

    // spt projection: fused tokenize gather + pos residual + row stats
    gemm_tc<2, 0, true, true, true, true, true, false, false, true><<<gg(MTOK, DIM), 256, GEMM_SMEM>>>(
        x, wtf + W_SPT_OFF, spt_b, pos, t, nullptr, nullptr, MTOK, DIM, 1280);

    for (int d = 0; d < 3; d++) {
        gemm_tc<3, 0, false, false, false, false, false, false, true, false><<<gg(MTOK, 768), 256, GEMM_SMEM>>>(
            t, wtf + W_QKV_OFF + (size_t)d * 768 * DIM, nullptr, nullptr, qkv,
            lnS + d * LNC_PER, lnB + d * LNC_PER, MTOK, 768, DIM);
        {
            dim3 grid((NTOK + 127) / 128, BATCH * NHEADS);
            attn_mma<<<grid, 256, ATT_SMEM>>>(scale + d * NHEADS);
        }
        gemm_tc<3, 0, true, true, false, true, false, false, false, true><<<gg(MTOK, DIM), 256, GEMM_SMEM>>>(
            attn, wtf + W_WOUT_OFF + (size_t)d * DIM * DIM, bout + d * DIM, t, t,
            nullptr, nullptr, MTOK, DIM, DIM);
        gemm_tc<3, 1, true, false, false, true, false, false, true, false><<<gg(MTOK, 1024), 256, GEMM_SMEM>>>(
            t, wtf + W_FF1_OFF + (size_t)d * 1024 * DIM, ff1_b + d * 1024, nullptr, ff,
            lnS + d * LNC_PER + 768, lnB + d * LNC_PER + 768, MTOK, 1024, DIM);
        gemm_tc<3, 0, true, true, false, true, false, false, false, true><<<gg(MTOK, DIM), 256, GEMM_SMEM>>>(
            ff, wtf + W_FF2_OFF + (size_t)d * DIM * 1024, ff2_b + d * DIM, t, t,
            nullptr, nullptr, MTOK, DIM, 1024);
    }

    // pix projection with fused untokenize + crop (writes d_out directly)
    gemm_tc<2, 0, true, false, false, false, false, true, false, false><<<gg(MTOK, DIM), 256, GEMM_SMEM>>>(
        t, wtf + W_PIX_OFF, pix_b, nullptr, (float*)d_out, nullptr, nullptr, MTOK, DIM, DIM);
}